// round 12
// baseline (speedup 1.0000x reference)
#include <cuda_runtime.h>
#include <cuda_bf16.h>
#include <math.h>

// Problem constants
#define BB   256
#define TT   512
#define EE   128
#define HD   128      // per-direction hidden
#define G4   512      // 4*HD
#define TAG  20
#define NCHAR 20000

typedef unsigned long long ull;

// packed f32x2 fma: acc = a*b + acc (elementwise on 2 packed floats)
#define FMA2(acc, a, b) asm("fma.rn.f32x2 %0, %1, %2, %0;" : "+l"(acc) : "l"(a), "l"(b))

__device__ __forceinline__ float pair_sum(ull u) {
    return __uint_as_float((unsigned)u) + __uint_as_float((unsigned)(u >> 32));
}
__device__ __forceinline__ float fast_tanh(float x) {
    float y;
    asm("tanh.approx.f32 %0, %1;" : "=f"(y) : "f"(x));
    return y;
}
__device__ __forceinline__ float fast_sigmoid(float x) {
    return fmaf(0.5f, fast_tanh(0.5f * x), 0.5f);
}

// -------- scratch (device globals; no runtime allocation) --------
__device__ float g_xw_f[(size_t)NCHAR * G4];       // per-char input gates, fwd (41MB)
__device__ float g_xw_b[(size_t)NCHAR * G4];       // per-char input gates, bwd (41MB)
__device__ float g_score_f[(size_t)TT * BB * TAG]; // fwd-direction emission part
__device__ float g_score_b[(size_t)TT * BB * TAG]; // bwd-direction emission part
__device__ float g_loss[BB];

// padding kernel: shifts ncu's fixed capture slot onto k2_lstm
__global__ void k_pad() {}

// =================================================================
// K1: per-character input projection tables (k-split, double-buffered)
// (verified passing in R11; unchanged)
// =================================================================
__global__ __launch_bounds__(256, 1) void k1_xw(
    const float* __restrict__ emb,
    const float* __restrict__ wih_f, const float* __restrict__ wih_b,
    const float* __restrict__ bih_f, const float* __restrict__ bhh_f,
    const float* __restrict__ bih_b, const float* __restrict__ bhh_b)
{
    __shared__ float esm[2][16 * 128];   // double-buffered 16-char embedding groups

    int tid   = threadIdx.x;
    int bid   = blockIdx.x;
    int chunk = bid & 15;
    int grp   = bid >> 4;
    int dir   = chunk >> 3;
    int jbase = (chunk & 7) * 64;
    const float* wih = dir ? wih_b : wih_f;
    float* xout = dir ? g_xw_b : g_xw_f;

    int w  = tid >> 5, l = tid & 31;
    int ks = l & 3;
    int id = w * 8 + (l >> 2);
    int cg4 = id >> 4;           // 0..3: chars cg4*4..+3 within the 16-group
    int rg  = id & 15;           // 0..15: rows jbase + rg*4..+3

    // weights in regs: 4 rows x 32 k (k-slice ks)
    ulonglong2 wreg[4][8];
#pragma unroll
    for (int r = 0; r < 4; r++)
#pragma unroll
        for (int q = 0; q < 8; q++)
            wreg[r][q] = ((const ulonglong2*)wih)[(size_t)(jbase + rg * 4 + r) * 32 + ks * 8 + q];

    float4 biasv;
    {
        const float4* b1 = (const float4*)(dir ? bih_b : bih_f);
        const float4* b2 = (const float4*)(dir ? bhh_b : bhh_f);
        float4 x = b1[(jbase >> 2) + rg], y = b2[(jbase >> 2) + rg];
        biasv = make_float4(x.x + y.x, x.y + y.y, x.z + y.z, x.w + y.w);
    }

    // preload first group into buffer 0
    ((float4*)esm[0])[tid]       = ((const float4*)emb)[(size_t)grp * 512 + tid];
    ((float4*)esm[0])[tid + 256] = ((const float4*)emb)[(size_t)grp * 512 + tid + 256];
    int pb = 0;

    for (int cg = grp; cg < 1250; cg += 8) {
        __syncthreads();   // buffer pb ready; prior readers of pb^1 done

        // prefetch next group into regs (clamped; harmless duplicate on last iter)
        int cgn = (cg + 8 < 1250) ? cg + 8 : grp;
        float4 p0 = ((const float4*)emb)[(size_t)cgn * 512 + tid];
        float4 p1 = ((const float4*)emb)[(size_t)cgn * 512 + tid + 256];

        ull acc[4][4];   // [char][row]
#pragma unroll
        for (int c = 0; c < 4; c++)
#pragma unroll
            for (int r = 0; r < 4; r++) acc[c][r] = 0ull;

        const ulonglong2* e2 = (const ulonglong2*)esm[pb];
#pragma unroll
        for (int q = 0; q < 8; q++) {
            ulonglong2 ev[4];
#pragma unroll
            for (int c = 0; c < 4; c++)
                ev[c] = e2[(cg4 * 4 + c) * 32 + ks * 8 + q];
#pragma unroll
            for (int c = 0; c < 4; c++)
#pragma unroll
                for (int r = 0; r < 4; r++) {
                    FMA2(acc[c][r], wreg[r][q].x, ev[c].x);
                    FMA2(acc[c][r], wreg[r][q].y, ev[c].y);
                }
        }

        // store prefetch to the other buffer (readers waited at loop-top barrier)
        ((float4*)esm[pb ^ 1])[tid]       = p0;
        ((float4*)esm[pb ^ 1])[tid + 256] = p1;

        float a[4][4];
#pragma unroll
        for (int c = 0; c < 4; c++)
#pragma unroll
            for (int r = 0; r < 4; r++) {
                float v = pair_sum(acc[c][r]);
                v += __shfl_xor_sync(0xffffffffu, v, 1);
                v += __shfl_xor_sync(0xffffffffu, v, 2);
                a[c][r] = v;
            }

        float4 o;
        o.x = a[ks][0] + biasv.x;
        o.y = a[ks][1] + biasv.y;
        o.z = a[ks][2] + biasv.z;
        o.w = a[ks][3] + biasv.w;
        int ch = cg * 16 + cg4 * 4 + ks;
        ((float4*)xout)[(size_t)ch * 128 + (jbase >> 2) + rg] = o;
        pb ^= 1;
    }
}

// =================================================================
// K2: BiLSTM recurrence + fused emission partials.
// (R=4,K=64,S=2) layout: warp w owns gate rows [w*64,(w+1)*64).
// Lane l: ks=l&1 (64-k half), rp=l>>1; rows base=w*64+rp*4.
// Rows base+0,1 weights in regs; base+2,3 from smem. 4 batches.
// Partials reduced across the ks pair with ONE shfl_xor butterfly.
// Staging (from R11): chars in smem once; xw gate inputs
// double-buffered via 2 coalesced LDG.128/thread/step.
// rows 0..127=i, 128..255=f, 256..383=g, 384..511=o.
// =================================================================
#define NB 4
// wsm 32768 | wl 2560 | hsm 512 | gsm 2048 | xst 4096 | csm 2048(int)
#define K2_SMEM_FLOATS (32768 + 2560 + 512 + 2048 + 4096 + 2048)
#define K2_SMEM_BYTES  (K2_SMEM_FLOATS * 4)

__global__ __launch_bounds__(256, 1) void k2_lstm(
    const int*   __restrict__ chars,
    const float* __restrict__ whh_f, const float* __restrict__ whh_b,
    const float* __restrict__ wlin)
{
    extern __shared__ float sm[];
    float* wsm = sm;            // 32768 floats: smem weight half (rows base+2,3)
    float* wl  = sm + 32768;    // 2560 : W_lin direction half
    float* hsm = sm + 35328;    // [nb][128]
    float* gsm = sm + 35840;    // [nb][512] activated gate exchange
    float* xst = sm + 37888;    // 2 x [nb][512] staged gate inputs
    int*   csm = (int*)(sm + 41984);  // [nb][512] chars

    int tid  = threadIdx.x;
    int bid  = blockIdx.x;
    int dir  = bid >> 6;
    int b0   = (bid & 63) * NB;
    const float* whh = dir ? whh_b : whh_f;
    const float* xw  = dir ? g_xw_b : g_xw_f;
    float* so        = dir ? g_score_b : g_score_f;

    int w  = tid >> 5, l = tid & 31;
    int ks = l & 1, rp = l >> 1;
    int base = w * 64 + rp * 4;

    // stage smem weight half: rows base+2,3 for every (w,rp), k-half per ks.
    // float4 slot i = ((ro*8 + ww)*16 + q)*32 + ll ; row = ww*64+(ll>>1)*4+2+ro,
    // k-granule = (ll&1)*16 + q  (q = 0..15)
    for (int i = tid; i < 8192; i += 256) {
        int ll = i & 31, q = (i >> 5) & 15, ww = (i >> 9) & 7, ro = i >> 12;
        int row = ww * 64 + (ll >> 1) * 4 + 2 + ro;
        int k4  = (ll & 1) * 16 + q;
        ((float4*)wsm)[i] = ((const float4*)whh)[(size_t)row * 32 + k4];
    }
    for (int i = tid; i < TAG * 128; i += 256) {
        int tg = i >> 7, k = i & 127;
        wl[i] = wlin[tg * 256 + dir * 128 + k];
    }
    for (int i = tid; i < NB * 32; i += 256)
        ((float4*)hsm)[i] = make_float4(0.f, 0.f, 0.f, 0.f);
    // chars for all NB batches, all steps
    for (int i = tid; i < NB * 512; i += 256)
        csm[i] = chars[(b0 + (i >> 9)) * TT + (i & 511)];

    // register weight rows base+0, base+1 (k-half ks): 2 x 64 floats = 128 regs
    ulonglong2 wreg[2][16];
#pragma unroll
    for (int r = 0; r < 2; r++)
#pragma unroll
        for (int q = 0; q < 16; q++)
            wreg[r][q] = ((const ulonglong2*)whh)[(size_t)(base + r) * 32 + ks * 16 + q];

    // initial stage: xstage[0] for the first timestep
    {
        int t0 = dir ? TT - 1 : 0;
        int c0 = __ldg(&chars[(b0 + 0) * TT + t0]);
        int c1 = __ldg(&chars[(b0 + 1) * TT + t0]);
        int c2 = __ldg(&chars[(b0 + 2) * TT + t0]);
        int c3 = __ldg(&chars[(b0 + 3) * TT + t0]);
        int cc[4] = {c0, c1, c2, c3};
#pragma unroll
        for (int it = 0; it < 2; it++) {
            int s4 = tid + it * 256;        // float4 slot 0..511
            int nb = s4 >> 7, q = s4 & 127;
            ((float4*)xst)[s4] = __ldg(&((const float4*)(xw + (size_t)cc[nb] * G4))[q]);
        }
    }
    __syncthreads();

    // c/h update ownership: every thread handles unit u = tid&127 for 2 batches
    int u  = tid & 127;
    int np = tid >> 7;
    float creg[2] = {0.f, 0.f};

    const ulonglong2* h2p = (const ulonglong2*)hsm;
    const ulonglong2* w2s = (const ulonglong2*)wsm;
    int gt = w >> 1;   // 0 i, 1 f, 2 g, 3 o
    int cur = 0;

    for (int step = 0; step < TT; step++) {
        int t = dir ? (TT - 1 - step) : step;

        // gate inputs for this lane's 2 output rows (base+2*ks+{0,1})
        float xg[2][NB];
#pragma unroll
        for (int r2 = 0; r2 < 2; r2++)
#pragma unroll
            for (int nb = 0; nb < NB; nb++)
                xg[r2][nb] = xst[cur * 2048 + nb * 512 + base + 2 * ks + r2];

        int cid[NB];
#pragma unroll
        for (int nb = 0; nb < NB; nb++) cid[nb] = csm[nb * 512 + t];

        // prefetch next step's gate inputs (coalesced float4 LDG)
        float4 pf0, pf1;
        if (step + 1 < TT) {
            int tn = dir ? (t - 1) : (t + 1);
            int s0 = tid, s1 = tid + 256;
            int cn0 = csm[(s0 >> 7) * 512 + tn];
            int cn1 = csm[(s1 >> 7) * 512 + tn];
            pf0 = __ldg(&((const float4*)(xw + (size_t)cn0 * G4))[s0 & 127]);
            pf1 = __ldg(&((const float4*)(xw + (size_t)cn1 * G4))[s1 & 127]);
        }

        ull acc[4][NB];
#pragma unroll
        for (int r = 0; r < 4; r++)
#pragma unroll
            for (int nb = 0; nb < NB; nb++) acc[r][nb] = 0ull;

#pragma unroll
        for (int q = 0; q < 16; q++) {
            ulonglong2 hh[NB];
#pragma unroll
            for (int nb = 0; nb < NB; nb++)
                hh[nb] = h2p[nb * 32 + ks * 16 + q];
            ulonglong2 ws2 = w2s[(w * 16 + q) * 32 + l];           // row base+2
            ulonglong2 ws3 = w2s[4096 + (w * 16 + q) * 32 + l];    // row base+3
#pragma unroll
            for (int nb = 0; nb < NB; nb++) {
                FMA2(acc[0][nb], wreg[0][q].x, hh[nb].x);
                FMA2(acc[0][nb], wreg[0][q].y, hh[nb].y);
                FMA2(acc[1][nb], wreg[1][q].x, hh[nb].x);
                FMA2(acc[1][nb], wreg[1][q].y, hh[nb].y);
                FMA2(acc[2][nb], ws2.x, hh[nb].x);
                FMA2(acc[2][nb], ws2.y, hh[nb].y);
                FMA2(acc[3][nb], ws3.x, hh[nb].x);
                FMA2(acc[3][nb], ws3.y, hh[nb].y);
            }
        }

        // butterfly across the ks pair: lane ks finalizes rows base+2*ks+{0,1}
#pragma unroll
        for (int r2 = 0; r2 < 2; r2++) {
            int r_own = 2 * ks + r2;        // row this lane writes
            int r_oth = 2 * (1 - ks) + r2;  // row the partner writes
#pragma unroll
            for (int nb = 0; nb < NB; nb++) {
                float a_own = pair_sum(acc[r_own][nb]);
                float a_oth = pair_sum(acc[r_oth][nb]);
                float got = __shfl_xor_sync(0xffffffffu, a_oth, 1);
                float s = a_own + got + xg[r2][nb];
                float v = (gt == 2) ? fast_tanh(s) : fast_sigmoid(s);
                gsm[nb * 512 + base + r_own] = v;
            }
        }

        // commit prefetch to the other stage buffer before the barrier
        if (step + 1 < TT) {
            ((float4*)(xst + (cur ^ 1) * 2048))[tid]       = pf0;
            ((float4*)(xst + (cur ^ 1) * 2048))[tid + 256] = pf1;
        }
        __syncthreads();

        // c/h update: unit u for 2 batches
#pragma unroll
        for (int e = 0; e < 2; e++) {
            int nb = np * 2 + e;
            float iv = gsm[nb * 512 + u];
            float fv = gsm[nb * 512 + 128 + u];
            float gg = gsm[nb * 512 + 256 + u];
            float oo = gsm[nb * 512 + 384 + u];
            float mm = (cid[nb] > 0) ? 1.f : 0.f;
            float cn = (fv * creg[e] + iv * gg) * mm;
            creg[e] = cn;
            hsm[nb * 128 + u] = oo * fast_tanh(cn) * mm;
        }
        __syncthreads();

        // emission partials: 20 tags x 8 k-chunks over warps 0..4
        if (tid < 160) {
            int tg = tid >> 3, p = tid & 7;
#pragma unroll
            for (int nb = 0; nb < NB; nb++) {
                float s = 0.f;
#pragma unroll
                for (int q = 0; q < 4; q++) {
                    float4 w4 = ((const float4*)wl)[tg * 32 + p * 4 + q];
                    float4 hv = ((const float4*)(hsm + nb * 128))[p * 4 + q];
                    s += w4.x * hv.x + w4.y * hv.y + w4.z * hv.z + w4.w * hv.w;
                }
                s += __shfl_down_sync(0xffffffffu, s, 4, 8);
                s += __shfl_down_sync(0xffffffffu, s, 2, 8);
                s += __shfl_down_sync(0xffffffffu, s, 1, 8);
                if (p == 0)
                    so[((size_t)t * BB + (b0 + nb)) * TAG + tg] = s;
            }
        }
        cur ^= 1;
    }
}

// =================================================================
// K3: CRF forward (log-partition) + partial-annotation gold score
// (verified passing in R11; unchanged)
// =================================================================
__global__ __launch_bounds__(64) void k3_crf(
    const int*   __restrict__ chars,
    const float* __restrict__ tags,
    const float* __restrict__ blin,
    const float* __restrict__ trans)
{
    __shared__ float tr[TAG * 21];
    __shared__ float tst[TAG], tsp[TAG], bl[TAG];
    __shared__ float abuf[2][2][TAG];
    __shared__ float gbuf[2][2][TAG];
    __shared__ float mbuf[2][2][TAG];

    int tid = threadIdx.x, w = tid >> 5, j = tid & 31;
    for (int i = tid; i < TAG * TAG; i += 64) {
        int rr = i / TAG, cc = i % TAG;
        tr[rr * 21 + cc] = trans[i];
    }
    if (tid < TAG) {
        tst[tid] = trans[tid * TAG + 1];       // trans[j][START]
        tsp[tid] = trans[2 * TAG + tid];       // trans[STOP][k]
        bl[tid]  = blin[tid];
    }
    __syncthreads();

    int b = blockIdx.x * 2 + w;
    bool act = (j < TAG);

    int L = 256;
#pragma unroll
    for (int base = 256; base < 512; base += 32) {
        int c = chars[b * TT + base + j];
        unsigned bal = __ballot_sync(0xffffffffu, c > 0);
        L += __popc(bal);
    }

    float trr[TAG];
#pragma unroll
    for (int k = 0; k < TAG; k++) trr[k] = act ? tr[j * 21 + k] : 0.f;

    int cur = 0;
    if (act) {
        float e0 = g_score_f[(size_t)b * TAG + j] + g_score_b[(size_t)b * TAG + j] + bl[j];
        float a0 = e0 + tst[j];
        float m0 = tags[((size_t)b * TT) * TAG + j];
        abuf[w][0][j] = a0;
        gbuf[w][0][j] = (m0 > 0.f) ? a0 : 0.f;
        mbuf[w][0][j] = m0;
    }
    __syncwarp();

    float nf = 0.f, nbv = 0.f, nm = 0.f;
    if (act && L > 1) {
        nf  = g_score_f[((size_t)1 * BB + b) * TAG + j];
        nbv = g_score_b[((size_t)1 * BB + b) * TAG + j];
        nm  = tags[((size_t)b * TT + 1) * TAG + j];
    }

    for (int t = 1; t < L; t++) {
        int nxt = cur ^ 1;
        if (act) {
            float emit  = nf + nbv + bl[j];
            float maskc = nm;
            if (t + 1 < TT) {
                nf  = g_score_f[((size_t)(t + 1) * BB + b) * TAG + j];
                nbv = g_score_b[((size_t)(t + 1) * BB + b) * TAG + j];
                nm  = tags[((size_t)b * TT + t + 1) * TAG + j];
            }
            float m = -1e30f;
#pragma unroll
            for (int k = 0; k < TAG; k++)
                m = fmaxf(m, abuf[w][cur][k] + trr[k]);
            float s = 0.f;
#pragma unroll
            for (int k = 0; k < TAG; k++)
                s += __expf(abuf[w][cur][k] + trr[k] - m);
            abuf[w][nxt][j] = emit + m + __logf(s);
            float gv = 0.f;
            if (maskc > 0.f) {
                float gm = -1e30f;
#pragma unroll
                for (int k = 0; k < TAG; k++) {
                    float v = gbuf[w][cur][k] + trr[k];
                    gm = fmaxf(gm, (mbuf[w][cur][k] > 0.f) ? v : -1e30f);
                }
                if (gm > -1e29f) {
                    float gs = 0.f;
#pragma unroll
                    for (int k = 0; k < TAG; k++) {
                        if (mbuf[w][cur][k] > 0.f)
                            gs += __expf(gbuf[w][cur][k] + trr[k] - gm);
                    }
                    gv = emit + gm + __logf(gs);
                }
            }
            gbuf[w][nxt][j] = gv;
            mbuf[w][nxt][j] = maskc;
        }
        __syncwarp();
        cur = nxt;
    }

    float av = act ? (abuf[w][cur][j] + tsp[j]) : -1e30f;
    float m = av;
#pragma unroll
    for (int o = 16; o; o >>= 1) m = fmaxf(m, __shfl_xor_sync(0xffffffffu, m, o));
    float p = (av > -1e29f) ? __expf(av - m) : 0.f;
#pragma unroll
    for (int o = 16; o; o >>= 1) p += __shfl_xor_sync(0xffffffffu, p, o);
    float fwd = m + __logf(p);

    float gj = act ? gbuf[w][cur][j] : 0.f;
    float ms = (gj != 0.f) ? 1.f : 0.f;
    float gx = (ms > 0.f) ? (gj + tsp[j]) : -1e30f;
    float gmx = gx, cnt = ms;
#pragma unroll
    for (int o = 16; o; o >>= 1) {
        gmx = fmaxf(gmx, __shfl_xor_sync(0xffffffffu, gmx, o));
        cnt += __shfl_xor_sync(0xffffffffu, cnt, o);
    }
    float gp = (gx > -1e29f) ? __expf(gx - gmx) : 0.f;
#pragma unroll
    for (int o = 16; o; o >>= 1) gp += __shfl_xor_sync(0xffffffffu, gp, o);
    float gsc = (cnt > 0.f) ? (gmx + __logf(gp)) : 0.f;

    if (j == 0) g_loss[b] = fwd - gsc;
}

// =================================================================
// K4: deterministic fixed-order reduction of per-batch losses
// =================================================================
__global__ void k4_reduce(float* out)
{
    int tid = threadIdx.x;
    if (tid < 32) {
        float s = 0.f;
#pragma unroll
        for (int q = 0; q < 8; q++) s += g_loss[tid + 32 * q];
#pragma unroll
        for (int o = 16; o; o >>= 1) s += __shfl_xor_sync(0xffffffffu, s, o);
        if (tid == 0) out[0] = s;
    }
}

// =================================================================
extern "C" void kernel_launch(void* const* d_in, const int* in_sizes, int n_in,
                              void* d_out, int out_size)
{
    const int*   chars = (const int*)  d_in[0];
    const float* tags  = (const float*)d_in[1];
    const float* emb   = (const float*)d_in[2];
    const float* wih_f = (const float*)d_in[3];
    const float* whh_f = (const float*)d_in[4];
    const float* bih_f = (const float*)d_in[5];
    const float* bhh_f = (const float*)d_in[6];
    const float* wih_b = (const float*)d_in[7];
    const float* whh_b = (const float*)d_in[8];
    const float* bih_b = (const float*)d_in[9];
    const float* bhh_b = (const float*)d_in[10];
    const float* wlin  = (const float*)d_in[11];
    const float* blin  = (const float*)d_in[12];
    const float* trans = (const float*)d_in[13];

    cudaFuncSetAttribute(k2_lstm, cudaFuncAttributeMaxDynamicSharedMemorySize, K2_SMEM_BYTES);

    // Launch order steers ncu's fixed capture slot onto k2_lstm:
    // k1, pad, pad, [k2 <- captured], k3, k4
    k1_xw<<<128, 256>>>(emb, wih_f, wih_b, bih_f, bhh_f, bih_b, bhh_b);
    k_pad<<<1, 32>>>();
    k_pad<<<1, 32>>>();
    k2_lstm<<<128, 256, K2_SMEM_BYTES>>>(chars, whh_f, whh_b, wlin);
    k3_crf<<<128, 64>>>(chars, tags, blin, trans);
    k4_reduce<<<1, 32>>>((float*)d_out);
}

// round 13
// speedup vs baseline: 1.1012x; 1.1012x over previous
#include <cuda_runtime.h>
#include <cuda_bf16.h>
#include <math.h>

// Problem constants
#define BB   256
#define TT   512
#define EE   128
#define HD   128      // per-direction hidden
#define G4   512      // 4*HD
#define TAG  20
#define NCHAR 20000

typedef unsigned long long ull;

// packed f32x2 fma: acc = a*b + acc (elementwise on 2 packed floats)
#define FMA2(acc, a, b) asm("fma.rn.f32x2 %0, %1, %2, %0;" : "+l"(acc) : "l"(a), "l"(b))

__device__ __forceinline__ float pair_sum(ull u) {
    return __uint_as_float((unsigned)u) + __uint_as_float((unsigned)(u >> 32));
}
__device__ __forceinline__ float fast_tanh(float x) {
    float y;
    asm("tanh.approx.f32 %0, %1;" : "=f"(y) : "f"(x));
    return y;
}
__device__ __forceinline__ float fast_sigmoid(float x) {
    return fmaf(0.5f, fast_tanh(0.5f * x), 0.5f);
}

// -------- scratch (device globals; no runtime allocation) --------
__device__ float g_xw_f[(size_t)NCHAR * G4];       // per-char input gates, fwd (41MB)
__device__ float g_xw_b[(size_t)NCHAR * G4];       // per-char input gates, bwd (41MB)
__device__ float g_score_f[(size_t)TT * BB * TAG]; // fwd-direction emission part
__device__ float g_score_b[(size_t)TT * BB * TAG]; // bwd-direction emission part
__device__ float g_loss[BB];

// padding kernel: shifts ncu's fixed capture slot (our 4th launch) onto k1
__global__ void k_pad() {}

// =================================================================
// K1: per-character input projection tables (k-split, double-buffered)
// (byte-identical to R11's passing version — this round it is the
//  PROFILED kernel, to locate the ~730us non-k2 residual)
// =================================================================
__global__ __launch_bounds__(256, 1) void k1_xw(
    const float* __restrict__ emb,
    const float* __restrict__ wih_f, const float* __restrict__ wih_b,
    const float* __restrict__ bih_f, const float* __restrict__ bhh_f,
    const float* __restrict__ bih_b, const float* __restrict__ bhh_b)
{
    __shared__ float esm[2][16 * 128];   // double-buffered 16-char embedding groups

    int tid   = threadIdx.x;
    int bid   = blockIdx.x;
    int chunk = bid & 15;
    int grp   = bid >> 4;
    int dir   = chunk >> 3;
    int jbase = (chunk & 7) * 64;
    const float* wih = dir ? wih_b : wih_f;
    float* xout = dir ? g_xw_b : g_xw_f;

    int w  = tid >> 5, l = tid & 31;
    int ks = l & 3;
    int id = w * 8 + (l >> 2);
    int cg4 = id >> 4;           // 0..3: chars cg4*4..+3 within the 16-group
    int rg  = id & 15;           // 0..15: rows jbase + rg*4..+3

    // weights in regs: 4 rows x 32 k (k-slice ks)
    ulonglong2 wreg[4][8];
#pragma unroll
    for (int r = 0; r < 4; r++)
#pragma unroll
        for (int q = 0; q < 8; q++)
            wreg[r][q] = ((const ulonglong2*)wih)[(size_t)(jbase + rg * 4 + r) * 32 + ks * 8 + q];

    float4 biasv;
    {
        const float4* b1 = (const float4*)(dir ? bih_b : bih_f);
        const float4* b2 = (const float4*)(dir ? bhh_b : bhh_f);
        float4 x = b1[(jbase >> 2) + rg], y = b2[(jbase >> 2) + rg];
        biasv = make_float4(x.x + y.x, x.y + y.y, x.z + y.z, x.w + y.w);
    }

    // preload first group into buffer 0
    ((float4*)esm[0])[tid]       = ((const float4*)emb)[(size_t)grp * 512 + tid];
    ((float4*)esm[0])[tid + 256] = ((const float4*)emb)[(size_t)grp * 512 + tid + 256];
    int pb = 0;

    for (int cg = grp; cg < 1250; cg += 8) {
        __syncthreads();   // buffer pb ready; prior readers of pb^1 done

        // prefetch next group into regs (clamped; harmless duplicate on last iter)
        int cgn = (cg + 8 < 1250) ? cg + 8 : grp;
        float4 p0 = ((const float4*)emb)[(size_t)cgn * 512 + tid];
        float4 p1 = ((const float4*)emb)[(size_t)cgn * 512 + tid + 256];

        ull acc[4][4];   // [char][row]
#pragma unroll
        for (int c = 0; c < 4; c++)
#pragma unroll
            for (int r = 0; r < 4; r++) acc[c][r] = 0ull;

        const ulonglong2* e2 = (const ulonglong2*)esm[pb];
#pragma unroll
        for (int q = 0; q < 8; q++) {
            ulonglong2 ev[4];
#pragma unroll
            for (int c = 0; c < 4; c++)
                ev[c] = e2[(cg4 * 4 + c) * 32 + ks * 8 + q];
#pragma unroll
            for (int c = 0; c < 4; c++)
#pragma unroll
                for (int r = 0; r < 4; r++) {
                    FMA2(acc[c][r], wreg[r][q].x, ev[c].x);
                    FMA2(acc[c][r], wreg[r][q].y, ev[c].y);
                }
        }

        // store prefetch to the other buffer (readers waited at loop-top barrier)
        ((float4*)esm[pb ^ 1])[tid]       = p0;
        ((float4*)esm[pb ^ 1])[tid + 256] = p1;

        float a[4][4];
#pragma unroll
        for (int c = 0; c < 4; c++)
#pragma unroll
            for (int r = 0; r < 4; r++) {
                float v = pair_sum(acc[c][r]);
                v += __shfl_xor_sync(0xffffffffu, v, 1);
                v += __shfl_xor_sync(0xffffffffu, v, 2);
                a[c][r] = v;
            }

        float4 o;
        o.x = a[ks][0] + biasv.x;
        o.y = a[ks][1] + biasv.y;
        o.z = a[ks][2] + biasv.z;
        o.w = a[ks][3] + biasv.w;
        int ch = cg * 16 + cg4 * 4 + ks;
        ((float4*)xout)[(size_t)ch * 128 + (jbase >> 2) + rg] = o;
        pb ^= 1;
    }
}

// =================================================================
// K2: BiLSTM recurrence + fused emission partials.
// REVERTED to R11's exact layout (best measured: k2 = 1.678 ms).
// R6/R11 broadcast layout beat both k-split variants (R7, R12) —
// kernel is latency-bound at 8 warps/SM; shorter per-step critical
// path wins over lower smem traffic.
// grid 128: bid<64 fwd batches 4*bid..+3; bid>=64 bwd.
// thread t: gate rows t (regs) and t+256 (smem).
// rows 0..127=i, 128..255=f, 256..383=g, 384..511=o.
// =================================================================
#define NB 4
// wb 32768 | wl 2560 | hsm 512 | psm 512 | xst 4096 | csm 2048(int)
#define K2_SMEM_FLOATS (32768 + 2560 + 512 + 512 + 4096 + 2048)
#define K2_SMEM_BYTES  (K2_SMEM_FLOATS * 4)

__global__ __launch_bounds__(256, 1) void k2_lstm(
    const int*   __restrict__ chars,
    const float* __restrict__ whh_f, const float* __restrict__ whh_b,
    const float* __restrict__ wlin)
{
    extern __shared__ float sm[];
    float* wb  = sm;            // 32768: [k4][row] float4 of rows 256..511
    float* wl  = sm + 32768;    // 2560 : W_lin direction half
    float* hsm = sm + 35328;    // [nb][128]
    float* psm = sm + 35840;    // [nb][128] i*g exchange
    float* xst = sm + 36352;    // 2 x [nb][512] staged gate inputs
    int*   csm = (int*)(sm + 40448);  // [nb][512] chars

    int tid  = threadIdx.x;
    int bid  = blockIdx.x;
    int dir  = bid >> 6;
    int b0   = (bid & 63) * NB;
    const float* whh = dir ? whh_b : whh_f;
    const float* xw  = dir ? g_xw_b : g_xw_f;
    float* so        = dir ? g_score_b : g_score_f;

    // smem weights: rows 256..511, layout [k4][r] float4 (conflict-free LDS.128)
    for (int i = tid; i < 32 * 256; i += 256) {
        int k4 = i >> 8, r = i & 255;
        ((float4*)wb)[i] = ((const float4*)whh)[(256 + r) * 32 + k4];
    }
    for (int i = tid; i < TAG * 128; i += 256) {
        int tg = i >> 7, k = i & 127;
        wl[i] = wlin[tg * 256 + dir * 128 + k];
    }
    for (int i = tid; i < NB * 32; i += 256)
        ((float4*)hsm)[i] = make_float4(0.f, 0.f, 0.f, 0.f);
    // chars for all NB batches, all steps (removes per-step chars LDG)
    for (int i = tid; i < NB * 512; i += 256)
        csm[i] = chars[(b0 + (i >> 9)) * TT + (i & 511)];

    // register weights for row tid, packed as 64 k-pairs
    ull waU[64];
#pragma unroll
    for (int p = 0; p < 64; p++) waU[p] = ((const ull*)whh)[(size_t)tid * 64 + p];

    // initial stage: xstage[0] for the first timestep
    {
        int t0 = dir ? TT - 1 : 0;
        int c0 = __ldg(&chars[(b0 + 0) * TT + t0]);
        int c1 = __ldg(&chars[(b0 + 1) * TT + t0]);
        int c2 = __ldg(&chars[(b0 + 2) * TT + t0]);
        int c3 = __ldg(&chars[(b0 + 3) * TT + t0]);
        int cc[4] = {c0, c1, c2, c3};
#pragma unroll
        for (int it = 0; it < 2; it++) {
            int s4 = tid + it * 256;        // float4 slot 0..511
            int nb = s4 >> 7, q = s4 & 127;
            ((float4*)xst)[s4] = __ldg(&((const float4*)(xw + (size_t)cc[nb] * G4))[q]);
        }
    }
    __syncthreads();

    float creg[NB];
#pragma unroll
    for (int nb = 0; nb < NB; nb++) creg[nb] = 0.f;

    const ulonglong2* wb4 = (const ulonglong2*)wb;
    int cur = 0;

    for (int step = 0; step < TT; step++) {
        int t = dir ? (TT - 1 - step) : step;

        // this step's gate inputs + masks from smem
        float xa[NB], xb[NB];
        int cid[NB];
#pragma unroll
        for (int nb = 0; nb < NB; nb++) {
            xa[nb]  = xst[cur * 2048 + nb * 512 + tid];
            xb[nb]  = xst[cur * 2048 + nb * 512 + 256 + tid];
            cid[nb] = csm[nb * 512 + t];
        }

        // prefetch next step's gate inputs (coalesced float4 LDG)
        float4 pf0, pf1;
        if (step + 1 < TT) {
            int tn = dir ? (t - 1) : (t + 1);
            int s0 = tid, s1 = tid + 256;
            int cn0 = csm[(s0 >> 7) * 512 + tn];
            int cn1 = csm[(s1 >> 7) * 512 + tn];
            pf0 = __ldg(&((const float4*)(xw + (size_t)cn0 * G4))[s0 & 127]);
            pf1 = __ldg(&((const float4*)(xw + (size_t)cn1 * G4))[s1 & 127]);
        }

        ull accA[NB], accB[NB];
#pragma unroll
        for (int nb = 0; nb < NB; nb++) { accA[nb] = 0ull; accB[nb] = 0ull; }

        const ulonglong2* h4p = (const ulonglong2*)hsm;
#pragma unroll
        for (int k4 = 0; k4 < 32; k4++) {
            ulonglong2 wB = wb4[k4 * 256 + tid];
            ull wA0 = waU[2 * k4], wA1 = waU[2 * k4 + 1];
#pragma unroll
            for (int nb = 0; nb < NB; nb++) {
                ulonglong2 h2 = h4p[nb * 32 + k4];
                FMA2(accA[nb], wA0, h2.x);
                FMA2(accA[nb], wA1, h2.y);
                FMA2(accB[nb], wB.x, h2.x);
                FMA2(accB[nb], wB.y, h2.y);
            }
        }

        float fv[NB], ov[NB];
#pragma unroll
        for (int nb = 0; nb < NB; nb++) {
            float aA = pair_sum(accA[nb]) + xa[nb];
            float aB = pair_sum(accB[nb]) + xb[nb];
            float sA = fast_sigmoid(aA);       // i (tid<128) / f (tid>=128)
            if (tid < 128) {
                psm[nb * 128 + tid] = sA * fast_tanh(aB);   // i*g
            } else {
                fv[nb] = sA;                    // f
                ov[nb] = fast_sigmoid(aB);      // o
            }
        }

        // commit prefetch to the other stage buffer before the barrier
        if (step + 1 < TT) {
            ((float4*)(xst + (cur ^ 1) * 2048))[tid]       = pf0;
            ((float4*)(xst + (cur ^ 1) * 2048))[tid + 256] = pf1;
        }
        __syncthreads();

        if (tid >= 128) {
            int u = tid - 128;
#pragma unroll
            for (int nb = 0; nb < NB; nb++) {
                float m  = (cid[nb] > 0) ? 1.f : 0.f;
                float cn = fv[nb] * creg[nb] + psm[nb * 128 + u];
                creg[nb] = cn * m;
                hsm[nb * 128 + u] = ov[nb] * fast_tanh(creg[nb]) * m;
            }
        }
        __syncthreads();

        // emission partials: 20 tags x 8 k-chunks over warps 0..4
        if (tid < 160) {
            int tg = tid >> 3, p = tid & 7;
#pragma unroll
            for (int nb = 0; nb < NB; nb++) {
                float s = 0.f;
#pragma unroll
                for (int q = 0; q < 4; q++) {
                    float4 w4 = ((const float4*)wl)[tg * 32 + p * 4 + q];
                    float4 hv = ((const float4*)(hsm + nb * 128))[p * 4 + q];
                    s += w4.x * hv.x + w4.y * hv.y + w4.z * hv.z + w4.w * hv.w;
                }
                s += __shfl_down_sync(0xffffffffu, s, 4, 8);
                s += __shfl_down_sync(0xffffffffu, s, 2, 8);
                s += __shfl_down_sync(0xffffffffu, s, 1, 8);
                if (p == 0)
                    so[((size_t)t * BB + (b0 + nb)) * TAG + tg] = s;
            }
        }
        cur ^= 1;
    }
}

// =================================================================
// K3: CRF forward (log-partition) + partial-annotation gold score
// (verified passing; unchanged)
// =================================================================
__global__ __launch_bounds__(64) void k3_crf(
    const int*   __restrict__ chars,
    const float* __restrict__ tags,
    const float* __restrict__ blin,
    const float* __restrict__ trans)
{
    __shared__ float tr[TAG * 21];
    __shared__ float tst[TAG], tsp[TAG], bl[TAG];
    __shared__ float abuf[2][2][TAG];
    __shared__ float gbuf[2][2][TAG];
    __shared__ float mbuf[2][2][TAG];

    int tid = threadIdx.x, w = tid >> 5, j = tid & 31;
    for (int i = tid; i < TAG * TAG; i += 64) {
        int rr = i / TAG, cc = i % TAG;
        tr[rr * 21 + cc] = trans[i];
    }
    if (tid < TAG) {
        tst[tid] = trans[tid * TAG + 1];       // trans[j][START]
        tsp[tid] = trans[2 * TAG + tid];       // trans[STOP][k]
        bl[tid]  = blin[tid];
    }
    __syncthreads();

    int b = blockIdx.x * 2 + w;
    bool act = (j < TAG);

    int L = 256;
#pragma unroll
    for (int base = 256; base < 512; base += 32) {
        int c = chars[b * TT + base + j];
        unsigned bal = __ballot_sync(0xffffffffu, c > 0);
        L += __popc(bal);
    }

    float trr[TAG];
#pragma unroll
    for (int k = 0; k < TAG; k++) trr[k] = act ? tr[j * 21 + k] : 0.f;

    int cur = 0;
    if (act) {
        float e0 = g_score_f[(size_t)b * TAG + j] + g_score_b[(size_t)b * TAG + j] + bl[j];
        float a0 = e0 + tst[j];
        float m0 = tags[((size_t)b * TT) * TAG + j];
        abuf[w][0][j] = a0;
        gbuf[w][0][j] = (m0 > 0.f) ? a0 : 0.f;
        mbuf[w][0][j] = m0;
    }
    __syncwarp();

    float nf = 0.f, nbv = 0.f, nm = 0.f;
    if (act && L > 1) {
        nf  = g_score_f[((size_t)1 * BB + b) * TAG + j];
        nbv = g_score_b[((size_t)1 * BB + b) * TAG + j];
        nm  = tags[((size_t)b * TT + 1) * TAG + j];
    }

    for (int t = 1; t < L; t++) {
        int nxt = cur ^ 1;
        if (act) {
            float emit  = nf + nbv + bl[j];
            float maskc = nm;
            if (t + 1 < TT) {
                nf  = g_score_f[((size_t)(t + 1) * BB + b) * TAG + j];
                nbv = g_score_b[((size_t)(t + 1) * BB + b) * TAG + j];
                nm  = tags[((size_t)b * TT + t + 1) * TAG + j];
            }
            float m = -1e30f;
#pragma unroll
            for (int k = 0; k < TAG; k++)
                m = fmaxf(m, abuf[w][cur][k] + trr[k]);
            float s = 0.f;
#pragma unroll
            for (int k = 0; k < TAG; k++)
                s += __expf(abuf[w][cur][k] + trr[k] - m);
            abuf[w][nxt][j] = emit + m + __logf(s);
            float gv = 0.f;
            if (maskc > 0.f) {
                float gm = -1e30f;
#pragma unroll
                for (int k = 0; k < TAG; k++) {
                    float v = gbuf[w][cur][k] + trr[k];
                    gm = fmaxf(gm, (mbuf[w][cur][k] > 0.f) ? v : -1e30f);
                }
                if (gm > -1e29f) {
                    float gs = 0.f;
#pragma unroll
                    for (int k = 0; k < TAG; k++) {
                        if (mbuf[w][cur][k] > 0.f)
                            gs += __expf(gbuf[w][cur][k] + trr[k] - gm);
                    }
                    gv = emit + gm + __logf(gs);
                }
            }
            gbuf[w][nxt][j] = gv;
            mbuf[w][nxt][j] = maskc;
        }
        __syncwarp();
        cur = nxt;
    }

    float av = act ? (abuf[w][cur][j] + tsp[j]) : -1e30f;
    float m = av;
#pragma unroll
    for (int o = 16; o; o >>= 1) m = fmaxf(m, __shfl_xor_sync(0xffffffffu, m, o));
    float p = (av > -1e29f) ? __expf(av - m) : 0.f;
#pragma unroll
    for (int o = 16; o; o >>= 1) p += __shfl_xor_sync(0xffffffffu, p, o);
    float fwd = m + __logf(p);

    float gj = act ? gbuf[w][cur][j] : 0.f;
    float ms = (gj != 0.f) ? 1.f : 0.f;
    float gx = (ms > 0.f) ? (gj + tsp[j]) : -1e30f;
    float gmx = gx, cnt = ms;
#pragma unroll
    for (int o = 16; o; o >>= 1) {
        gmx = fmaxf(gmx, __shfl_xor_sync(0xffffffffu, gmx, o));
        cnt += __shfl_xor_sync(0xffffffffu, cnt, o);
    }
    float gp = (gx > -1e29f) ? __expf(gx - gmx) : 0.f;
#pragma unroll
    for (int o = 16; o; o >>= 1) gp += __shfl_xor_sync(0xffffffffu, gp, o);
    float gsc = (cnt > 0.f) ? (gmx + __logf(gp)) : 0.f;

    if (j == 0) g_loss[b] = fwd - gsc;
}

// =================================================================
// K4: deterministic fixed-order reduction of per-batch losses
// =================================================================
__global__ void k4_reduce(float* out)
{
    int tid = threadIdx.x;
    if (tid < 32) {
        float s = 0.f;
#pragma unroll
        for (int q = 0; q < 8; q++) s += g_loss[tid + 32 * q];
#pragma unroll
        for (int o = 16; o; o >>= 1) s += __shfl_xor_sync(0xffffffffu, s, o);
        if (tid == 0) out[0] = s;
    }
}

// =================================================================
extern "C" void kernel_launch(void* const* d_in, const int* in_sizes, int n_in,
                              void* d_out, int out_size)
{
    const int*   chars = (const int*)  d_in[0];
    const float* tags  = (const float*)d_in[1];
    const float* emb   = (const float*)d_in[2];
    const float* wih_f = (const float*)d_in[3];
    const float* whh_f = (const float*)d_in[4];
    const float* bih_f = (const float*)d_in[5];
    const float* bhh_f = (const float*)d_in[6];
    const float* wih_b = (const float*)d_in[7];
    const float* whh_b = (const float*)d_in[8];
    const float* bih_b = (const float*)d_in[9];
    const float* bhh_b = (const float*)d_in[10];
    const float* wlin  = (const float*)d_in[11];
    const float* blin  = (const float*)d_in[12];
    const float* trans = (const float*)d_in[13];

    cudaFuncSetAttribute(k2_lstm, cudaFuncAttributeMaxDynamicSharedMemorySize, K2_SMEM_BYTES);

    // Launch order steers ncu's fixed capture slot (our 4th launch) onto K1
    // this round, to decompose the ~730us non-k2 residual:
    // pad, pad, pad, [k1 <- captured], k2, k3, k4
    k_pad<<<1, 32>>>();
    k_pad<<<1, 32>>>();
    k_pad<<<1, 32>>>();
    k1_xw<<<128, 256>>>(emb, wih_f, wih_b, bih_f, bhh_f, bih_b, bhh_b);
    k2_lstm<<<128, 256, K2_SMEM_BYTES>>>(chars, whh_f, whh_b, wlin);
    k3_crf<<<128, 64>>>(chars, tags, blin, trans);
    k4_reduce<<<1, 32>>>((float*)d_out);
}

// round 14
// speedup vs baseline: 1.1561x; 1.0498x over previous
#include <cuda_runtime.h>
#include <cuda_bf16.h>
#include <math.h>

// Problem constants
#define BB   256
#define TT   512
#define EE   128
#define HD   128      // per-direction hidden
#define G4   512      // 4*HD
#define TAG  20
#define NCHAR 20000

typedef unsigned long long ull;

// packed f32x2 fma: acc = a*b + acc (elementwise on 2 packed floats)
#define FMA2(acc, a, b) asm("fma.rn.f32x2 %0, %1, %2, %0;" : "+l"(acc) : "l"(a), "l"(b))

__device__ __forceinline__ float pair_sum(ull u) {
    return __uint_as_float((unsigned)u) + __uint_as_float((unsigned)(u >> 32));
}
__device__ __forceinline__ float fast_tanh(float x) {
    float y;
    asm("tanh.approx.f32 %0, %1;" : "=f"(y) : "f"(x));
    return y;
}
__device__ __forceinline__ float fast_sigmoid(float x) {
    return fmaf(0.5f, fast_tanh(0.5f * x), 0.5f);
}

// -------- scratch (device globals; no runtime allocation) --------
__device__ float g_xw_f[(size_t)NCHAR * G4];       // per-char input gates, fwd (41MB)
__device__ float g_xw_b[(size_t)NCHAR * G4];       // per-char input gates, bwd (41MB)
__device__ float g_score_f[(size_t)TT * BB * TAG]; // fwd-direction emission part
__device__ float g_score_b[(size_t)TT * BB * TAG]; // bwd-direction emission part
__device__ float g_loss[BB];

// padding kernel: keeps ncu's fixed capture slot (our 4th launch) on k3
__global__ void k_pad() {}

// =================================================================
// K1: per-character input projection tables (k-split, double-buffered)
// R13-profiled version; only change: grid 144 (16 chunks x 9 groups)
// to cover all 148 SMs instead of leaving 20 idle.
// =================================================================
__global__ __launch_bounds__(256, 1) void k1_xw(
    const float* __restrict__ emb,
    const float* __restrict__ wih_f, const float* __restrict__ wih_b,
    const float* __restrict__ bih_f, const float* __restrict__ bhh_f,
    const float* __restrict__ bih_b, const float* __restrict__ bhh_b)
{
    __shared__ float esm[2][16 * 128];   // double-buffered 16-char embedding groups

    int tid   = threadIdx.x;
    int bid   = blockIdx.x;
    int chunk = bid % 16;
    int grp   = bid / 16;        // 0..8
    int dir   = chunk >> 3;
    int jbase = (chunk & 7) * 64;
    const float* wih = dir ? wih_b : wih_f;
    float* xout = dir ? g_xw_b : g_xw_f;

    int w  = tid >> 5, l = tid & 31;
    int ks = l & 3;
    int id = w * 8 + (l >> 2);
    int cg4 = id >> 4;           // 0..3: chars cg4*4..+3 within the 16-group
    int rg  = id & 15;           // 0..15: rows jbase + rg*4..+3

    // weights in regs: 4 rows x 32 k (k-slice ks)
    ulonglong2 wreg[4][8];
#pragma unroll
    for (int r = 0; r < 4; r++)
#pragma unroll
        for (int q = 0; q < 8; q++)
            wreg[r][q] = ((const ulonglong2*)wih)[(size_t)(jbase + rg * 4 + r) * 32 + ks * 8 + q];

    float4 biasv;
    {
        const float4* b1 = (const float4*)(dir ? bih_b : bih_f);
        const float4* b2 = (const float4*)(dir ? bhh_b : bhh_f);
        float4 x = b1[(jbase >> 2) + rg], y = b2[(jbase >> 2) + rg];
        biasv = make_float4(x.x + y.x, x.y + y.y, x.z + y.z, x.w + y.w);
    }

    // preload first group into buffer 0
    ((float4*)esm[0])[tid]       = ((const float4*)emb)[(size_t)grp * 512 + tid];
    ((float4*)esm[0])[tid + 256] = ((const float4*)emb)[(size_t)grp * 512 + tid + 256];
    int pb = 0;

    for (int cg = grp; cg < 1250; cg += 9) {
        __syncthreads();   // buffer pb ready; prior readers of pb^1 done

        // prefetch next group into regs (clamped; harmless duplicate on last iter)
        int cgn = (cg + 9 < 1250) ? cg + 9 : grp;
        float4 p0 = ((const float4*)emb)[(size_t)cgn * 512 + tid];
        float4 p1 = ((const float4*)emb)[(size_t)cgn * 512 + tid + 256];

        ull acc[4][4];   // [char][row]
#pragma unroll
        for (int c = 0; c < 4; c++)
#pragma unroll
            for (int r = 0; r < 4; r++) acc[c][r] = 0ull;

        const ulonglong2* e2 = (const ulonglong2*)esm[pb];
#pragma unroll
        for (int q = 0; q < 8; q++) {
            ulonglong2 ev[4];
#pragma unroll
            for (int c = 0; c < 4; c++)
                ev[c] = e2[(cg4 * 4 + c) * 32 + ks * 8 + q];
#pragma unroll
            for (int c = 0; c < 4; c++)
#pragma unroll
                for (int r = 0; r < 4; r++) {
                    FMA2(acc[c][r], wreg[r][q].x, ev[c].x);
                    FMA2(acc[c][r], wreg[r][q].y, ev[c].y);
                }
        }

        // store prefetch to the other buffer (readers waited at loop-top barrier)
        ((float4*)esm[pb ^ 1])[tid]       = p0;
        ((float4*)esm[pb ^ 1])[tid + 256] = p1;

        float a[4][4];
#pragma unroll
        for (int c = 0; c < 4; c++)
#pragma unroll
            for (int r = 0; r < 4; r++) {
                float v = pair_sum(acc[c][r]);
                v += __shfl_xor_sync(0xffffffffu, v, 1);
                v += __shfl_xor_sync(0xffffffffu, v, 2);
                a[c][r] = v;
            }

        float4 o;
        o.x = a[ks][0] + biasv.x;
        o.y = a[ks][1] + biasv.y;
        o.z = a[ks][2] + biasv.z;
        o.w = a[ks][3] + biasv.w;
        int ch = cg * 16 + cg4 * 4 + ks;
        ((float4*)xout)[(size_t)ch * 128 + (jbase >> 2) + rg] = o;
        pb ^= 1;
    }
}

// =================================================================
// K2: BiLSTM recurrence + fused emission partials.
// R11's exact layout (best measured: k2 = 1.678 ms). Unchanged.
// =================================================================
#define NB 4
// wb 32768 | wl 2560 | hsm 512 | psm 512 | xst 4096 | csm 2048(int)
#define K2_SMEM_FLOATS (32768 + 2560 + 512 + 512 + 4096 + 2048)
#define K2_SMEM_BYTES  (K2_SMEM_FLOATS * 4)

__global__ __launch_bounds__(256, 1) void k2_lstm(
    const int*   __restrict__ chars,
    const float* __restrict__ whh_f, const float* __restrict__ whh_b,
    const float* __restrict__ wlin)
{
    extern __shared__ float sm[];
    float* wb  = sm;            // 32768: [k4][row] float4 of rows 256..511
    float* wl  = sm + 32768;    // 2560 : W_lin direction half
    float* hsm = sm + 35328;    // [nb][128]
    float* psm = sm + 35840;    // [nb][128] i*g exchange
    float* xst = sm + 36352;    // 2 x [nb][512] staged gate inputs
    int*   csm = (int*)(sm + 40448);  // [nb][512] chars

    int tid  = threadIdx.x;
    int bid  = blockIdx.x;
    int dir  = bid >> 6;
    int b0   = (bid & 63) * NB;
    const float* whh = dir ? whh_b : whh_f;
    const float* xw  = dir ? g_xw_b : g_xw_f;
    float* so        = dir ? g_score_b : g_score_f;

    // smem weights: rows 256..511, layout [k4][r] float4 (conflict-free LDS.128)
    for (int i = tid; i < 32 * 256; i += 256) {
        int k4 = i >> 8, r = i & 255;
        ((float4*)wb)[i] = ((const float4*)whh)[(256 + r) * 32 + k4];
    }
    for (int i = tid; i < TAG * 128; i += 256) {
        int tg = i >> 7, k = i & 127;
        wl[i] = wlin[tg * 256 + dir * 128 + k];
    }
    for (int i = tid; i < NB * 32; i += 256)
        ((float4*)hsm)[i] = make_float4(0.f, 0.f, 0.f, 0.f);
    // chars for all NB batches, all steps
    for (int i = tid; i < NB * 512; i += 256)
        csm[i] = chars[(b0 + (i >> 9)) * TT + (i & 511)];

    // register weights for row tid, packed as 64 k-pairs
    ull waU[64];
#pragma unroll
    for (int p = 0; p < 64; p++) waU[p] = ((const ull*)whh)[(size_t)tid * 64 + p];

    // initial stage: xstage[0] for the first timestep
    {
        int t0 = dir ? TT - 1 : 0;
        int c0 = __ldg(&chars[(b0 + 0) * TT + t0]);
        int c1 = __ldg(&chars[(b0 + 1) * TT + t0]);
        int c2 = __ldg(&chars[(b0 + 2) * TT + t0]);
        int c3 = __ldg(&chars[(b0 + 3) * TT + t0]);
        int cc[4] = {c0, c1, c2, c3};
#pragma unroll
        for (int it = 0; it < 2; it++) {
            int s4 = tid + it * 256;        // float4 slot 0..511
            int nb = s4 >> 7, q = s4 & 127;
            ((float4*)xst)[s4] = __ldg(&((const float4*)(xw + (size_t)cc[nb] * G4))[q]);
        }
    }
    __syncthreads();

    float creg[NB];
#pragma unroll
    for (int nb = 0; nb < NB; nb++) creg[nb] = 0.f;

    const ulonglong2* wb4 = (const ulonglong2*)wb;
    int cur = 0;

    for (int step = 0; step < TT; step++) {
        int t = dir ? (TT - 1 - step) : step;

        // this step's gate inputs + masks from smem
        float xa[NB], xb[NB];
        int cid[NB];
#pragma unroll
        for (int nb = 0; nb < NB; nb++) {
            xa[nb]  = xst[cur * 2048 + nb * 512 + tid];
            xb[nb]  = xst[cur * 2048 + nb * 512 + 256 + tid];
            cid[nb] = csm[nb * 512 + t];
        }

        // prefetch next step's gate inputs (coalesced float4 LDG)
        float4 pf0, pf1;
        if (step + 1 < TT) {
            int tn = dir ? (t - 1) : (t + 1);
            int s0 = tid, s1 = tid + 256;
            int cn0 = csm[(s0 >> 7) * 512 + tn];
            int cn1 = csm[(s1 >> 7) * 512 + tn];
            pf0 = __ldg(&((const float4*)(xw + (size_t)cn0 * G4))[s0 & 127]);
            pf1 = __ldg(&((const float4*)(xw + (size_t)cn1 * G4))[s1 & 127]);
        }

        ull accA[NB], accB[NB];
#pragma unroll
        for (int nb = 0; nb < NB; nb++) { accA[nb] = 0ull; accB[nb] = 0ull; }

        const ulonglong2* h4p = (const ulonglong2*)hsm;
#pragma unroll
        for (int k4 = 0; k4 < 32; k4++) {
            ulonglong2 wB = wb4[k4 * 256 + tid];
            ull wA0 = waU[2 * k4], wA1 = waU[2 * k4 + 1];
#pragma unroll
            for (int nb = 0; nb < NB; nb++) {
                ulonglong2 h2 = h4p[nb * 32 + k4];
                FMA2(accA[nb], wA0, h2.x);
                FMA2(accA[nb], wA1, h2.y);
                FMA2(accB[nb], wB.x, h2.x);
                FMA2(accB[nb], wB.y, h2.y);
            }
        }

        float fv[NB], ov[NB];
#pragma unroll
        for (int nb = 0; nb < NB; nb++) {
            float aA = pair_sum(accA[nb]) + xa[nb];
            float aB = pair_sum(accB[nb]) + xb[nb];
            float sA = fast_sigmoid(aA);       // i (tid<128) / f (tid>=128)
            if (tid < 128) {
                psm[nb * 128 + tid] = sA * fast_tanh(aB);   // i*g
            } else {
                fv[nb] = sA;                    // f
                ov[nb] = fast_sigmoid(aB);      // o
            }
        }

        // commit prefetch to the other stage buffer before the barrier
        if (step + 1 < TT) {
            ((float4*)(xst + (cur ^ 1) * 2048))[tid]       = pf0;
            ((float4*)(xst + (cur ^ 1) * 2048))[tid + 256] = pf1;
        }
        __syncthreads();

        if (tid >= 128) {
            int u = tid - 128;
#pragma unroll
            for (int nb = 0; nb < NB; nb++) {
                float m  = (cid[nb] > 0) ? 1.f : 0.f;
                float cn = fv[nb] * creg[nb] + psm[nb * 128 + u];
                creg[nb] = cn * m;
                hsm[nb * 128 + u] = ov[nb] * fast_tanh(creg[nb]) * m;
            }
        }
        __syncthreads();

        // emission partials: 20 tags x 8 k-chunks over warps 0..4
        if (tid < 160) {
            int tg = tid >> 3, p = tid & 7;
#pragma unroll
            for (int nb = 0; nb < NB; nb++) {
                float s = 0.f;
#pragma unroll
                for (int q = 0; q < 4; q++) {
                    float4 w4 = ((const float4*)wl)[tg * 32 + p * 4 + q];
                    float4 hv = ((const float4*)(hsm + nb * 128))[p * 4 + q];
                    s += w4.x * hv.x + w4.y * hv.y + w4.z * hv.z + w4.w * hv.w;
                }
                s += __shfl_down_sync(0xffffffffu, s, 4, 8);
                s += __shfl_down_sync(0xffffffffu, s, 2, 8);
                s += __shfl_down_sync(0xffffffffu, s, 1, 8);
                if (p == 0)
                    so[((size_t)t * BB + (b0 + nb)) * TAG + tg] = s;
            }
        }
        cur ^= 1;
    }
}

// =================================================================
// K3: CRF forward + partial-annotation gold — SPLIT-ROLE version.
// The alpha and gold recurrences are mutually independent, so run
// them on separate warps to halve the per-step serial chain.
// grid 128, block 128 (4 warps): warp w -> batch b0+(w&1),
// role w>>1 (0 = alpha/forward-score, 1 = gold score).
// =================================================================
__global__ __launch_bounds__(128) void k3_crf(
    const int*   __restrict__ chars,
    const float* __restrict__ tags,
    const float* __restrict__ blin,
    const float* __restrict__ trans)
{
    __shared__ float tr[TAG * 21];
    __shared__ float tst[TAG], tsp[TAG], bl[TAG];
    __shared__ float abuf[2][2][TAG];   // [batch-slot][pingpong][tag]
    __shared__ float gbuf[2][2][TAG];
    __shared__ float mbuf[2][2][TAG];
    __shared__ float res[2][2];         // [batch-slot][role]

    int tid = threadIdx.x, w = tid >> 5, j = tid & 31;
    int bs = w & 1;           // batch slot 0/1
    int role = w >> 1;        // 0 = alpha, 1 = gold
    for (int i = tid; i < TAG * TAG; i += 128) {
        int rr = i / TAG, cc = i % TAG;
        tr[rr * 21 + cc] = trans[i];
    }
    if (tid < TAG) {
        tst[tid] = trans[tid * TAG + 1];       // trans[j][START]
        tsp[tid] = trans[2 * TAG + tid];       // trans[STOP][k]
        bl[tid]  = blin[tid];
    }
    __syncthreads();

    int b = blockIdx.x * 2 + bs;
    bool act = (j < TAG);

    // sequence length (valid prefix; min length is 256)
    int L = 256;
#pragma unroll
    for (int base = 256; base < 512; base += 32) {
        int c = chars[b * TT + base + j];
        unsigned bal = __ballot_sync(0xffffffffu, c > 0);
        L += __popc(bal);
    }

    float trr[TAG];
#pragma unroll
    for (int k = 0; k < TAG; k++) trr[k] = act ? tr[j * 21 + k] : 0.f;

    int cur = 0;

    if (role == 0) {
        // ---------------- alpha (log-partition) warp ----------------
        if (act) {
            float e0 = g_score_f[(size_t)b * TAG + j] + g_score_b[(size_t)b * TAG + j] + bl[j];
            abuf[bs][0][j] = e0 + tst[j];
        }
        __syncwarp();

        float nf = 0.f, nbv = 0.f;
        if (act && L > 1) {
            nf  = g_score_f[((size_t)1 * BB + b) * TAG + j];
            nbv = g_score_b[((size_t)1 * BB + b) * TAG + j];
        }

        for (int t = 1; t < L; t++) {
            int nxt = cur ^ 1;
            if (act) {
                float emit = nf + nbv + bl[j];
                if (t + 1 < TT) {
                    nf  = g_score_f[((size_t)(t + 1) * BB + b) * TAG + j];
                    nbv = g_score_b[((size_t)(t + 1) * BB + b) * TAG + j];
                }
                float m = -1e30f;
#pragma unroll
                for (int k = 0; k < TAG; k++)
                    m = fmaxf(m, abuf[bs][cur][k] + trr[k]);
                float s = 0.f;
#pragma unroll
                for (int k = 0; k < TAG; k++)
                    s += __expf(abuf[bs][cur][k] + trr[k] - m);
                abuf[bs][nxt][j] = emit + m + __logf(s);
            }
            __syncwarp();
            cur = nxt;
        }

        // forward_score = lse_k(alpha[k] + trans[STOP][k])
        float av = act ? (abuf[bs][cur][j] + tsp[j]) : -1e30f;
        float m = av;
#pragma unroll
        for (int o = 16; o; o >>= 1) m = fmaxf(m, __shfl_xor_sync(0xffffffffu, m, o));
        float p = (av > -1e29f) ? __expf(av - m) : 0.f;
#pragma unroll
        for (int o = 16; o; o >>= 1) p += __shfl_xor_sync(0xffffffffu, p, o);
        if (j == 0) res[bs][0] = m + __logf(p);
    } else {
        // ---------------- gold (partial annotation) warp ----------------
        if (act) {
            float e0 = g_score_f[(size_t)b * TAG + j] + g_score_b[(size_t)b * TAG + j] + bl[j];
            float a0 = e0 + tst[j];
            float m0 = tags[((size_t)b * TT) * TAG + j];
            gbuf[bs][0][j] = (m0 > 0.f) ? a0 : 0.f;
            mbuf[bs][0][j] = m0;
        }
        __syncwarp();

        float nf = 0.f, nbv = 0.f, nm = 0.f;
        if (act && L > 1) {
            nf  = g_score_f[((size_t)1 * BB + b) * TAG + j];
            nbv = g_score_b[((size_t)1 * BB + b) * TAG + j];
            nm  = tags[((size_t)b * TT + 1) * TAG + j];
        }

        for (int t = 1; t < L; t++) {
            int nxt = cur ^ 1;
            if (act) {
                float emit  = nf + nbv + bl[j];
                float maskc = nm;
                if (t + 1 < TT) {
                    nf  = g_score_f[((size_t)(t + 1) * BB + b) * TAG + j];
                    nbv = g_score_b[((size_t)(t + 1) * BB + b) * TAG + j];
                    nm  = tags[((size_t)b * TT + t + 1) * TAG + j];
                }
                float gv = 0.f;
                if (maskc > 0.f) {
                    float gm = -1e30f;
#pragma unroll
                    for (int k = 0; k < TAG; k++) {
                        float v = gbuf[bs][cur][k] + trr[k];
                        gm = fmaxf(gm, (mbuf[bs][cur][k] > 0.f) ? v : -1e30f);
                    }
                    if (gm > -1e29f) {
                        float gs = 0.f;
#pragma unroll
                        for (int k = 0; k < TAG; k++) {
                            if (mbuf[bs][cur][k] > 0.f)
                                gs += __expf(gbuf[bs][cur][k] + trr[k] - gm);
                        }
                        gv = emit + gm + __logf(gs);
                    }
                }
                gbuf[bs][nxt][j] = gv;
                mbuf[bs][nxt][j] = maskc;
            }
            __syncwarp();
            cur = nxt;
        }

        // gold_score = masked lse over tags with gold != 0
        float gj = act ? gbuf[bs][cur][j] : 0.f;
        float ms = (gj != 0.f) ? 1.f : 0.f;
        float gx = (ms > 0.f) ? (gj + tsp[j]) : -1e30f;
        float gmx = gx, cnt = ms;
#pragma unroll
        for (int o = 16; o; o >>= 1) {
            gmx = fmaxf(gmx, __shfl_xor_sync(0xffffffffu, gmx, o));
            cnt += __shfl_xor_sync(0xffffffffu, cnt, o);
        }
        float gp = (gx > -1e29f) ? __expf(gx - gmx) : 0.f;
#pragma unroll
        for (int o = 16; o; o >>= 1) gp += __shfl_xor_sync(0xffffffffu, gp, o);
        if (j == 0) res[bs][1] = (cnt > 0.f) ? (gmx + __logf(gp)) : 0.f;
    }

    __syncthreads();
    if (tid < 2)
        g_loss[blockIdx.x * 2 + tid] = res[tid][0] - res[tid][1];
}

// =================================================================
// K4: deterministic fixed-order reduction of per-batch losses
// =================================================================
__global__ void k4_reduce(float* out)
{
    int tid = threadIdx.x;
    if (tid < 32) {
        float s = 0.f;
#pragma unroll
        for (int q = 0; q < 8; q++) s += g_loss[tid + 32 * q];
#pragma unroll
        for (int o = 16; o; o >>= 1) s += __shfl_xor_sync(0xffffffffu, s, o);
        if (tid == 0) out[0] = s;
    }
}

// =================================================================
extern "C" void kernel_launch(void* const* d_in, const int* in_sizes, int n_in,
                              void* d_out, int out_size)
{
    const int*   chars = (const int*)  d_in[0];
    const float* tags  = (const float*)d_in[1];
    const float* emb   = (const float*)d_in[2];
    const float* wih_f = (const float*)d_in[3];
    const float* whh_f = (const float*)d_in[4];
    const float* bih_f = (const float*)d_in[5];
    const float* bhh_f = (const float*)d_in[6];
    const float* wih_b = (const float*)d_in[7];
    const float* whh_b = (const float*)d_in[8];
    const float* bih_b = (const float*)d_in[9];
    const float* bhh_b = (const float*)d_in[10];
    const float* wlin  = (const float*)d_in[11];
    const float* blin  = (const float*)d_in[12];
    const float* trans = (const float*)d_in[13];

    cudaFuncSetAttribute(k2_lstm, cudaFuncAttributeMaxDynamicSharedMemorySize, K2_SMEM_BYTES);

    // Launch order puts the NEW k3 in ncu's captured 4th slot:
    // k1, pad, k2, [k3 <- captured], k4
    k1_xw<<<144, 256>>>(emb, wih_f, wih_b, bih_f, bhh_f, bih_b, bhh_b);
    k_pad<<<1, 32>>>();
    k2_lstm<<<128, 256, K2_SMEM_BYTES>>>(chars, whh_f, whh_b, wlin);
    k3_crf<<<128, 128>>>(chars, tags, blin, trans);
    k4_reduce<<<1, 32>>>((float*)d_out);
}

// round 15
// speedup vs baseline: 1.1832x; 1.0235x over previous
#include <cuda_runtime.h>
#include <cuda_bf16.h>
#include <math.h>

// Problem constants
#define BB   256
#define TT   512
#define EE   128
#define HD   128      // per-direction hidden
#define G4   512      // 4*HD
#define TAG  20
#define NCHAR 20000

typedef unsigned long long ull;

// packed f32x2 fma: acc = a*b + acc (elementwise on 2 packed floats)
#define FMA2(acc, a, b) asm("fma.rn.f32x2 %0, %1, %2, %0;" : "+l"(acc) : "l"(a), "l"(b))

__device__ __forceinline__ float pair_sum(ull u) {
    return __uint_as_float((unsigned)u) + __uint_as_float((unsigned)(u >> 32));
}
__device__ __forceinline__ float fast_tanh(float x) {
    float y;
    asm("tanh.approx.f32 %0, %1;" : "=f"(y) : "f"(x));
    return y;
}
__device__ __forceinline__ float fast_sigmoid(float x) {
    return fmaf(0.5f, fast_tanh(0.5f * x), 0.5f);
}

// -------- scratch (device globals; no runtime allocation) --------
__device__ float g_xw_f[(size_t)NCHAR * G4];       // per-char input gates, fwd (41MB)
__device__ float g_xw_b[(size_t)NCHAR * G4];       // per-char input gates, bwd (41MB)
__device__ float g_score_f[(size_t)TT * BB * TAG]; // fwd-direction emission part
__device__ float g_score_b[(size_t)TT * BB * TAG]; // bwd-direction emission part
__device__ float g_loss[BB];

// padding kernel: keeps ncu's fixed capture slot (our 4th launch) on k3
__global__ void k_pad() {}

// =================================================================
// K1: per-character input projection tables (k-split, double-buffered)
// 144 CTAs (16 chunks x 9 cg-groups). Measured-good in R14; unchanged.
// =================================================================
__global__ __launch_bounds__(256, 1) void k1_xw(
    const float* __restrict__ emb,
    const float* __restrict__ wih_f, const float* __restrict__ wih_b,
    const float* __restrict__ bih_f, const float* __restrict__ bhh_f,
    const float* __restrict__ bih_b, const float* __restrict__ bhh_b)
{
    __shared__ float esm[2][16 * 128];   // double-buffered 16-char embedding groups

    int tid   = threadIdx.x;
    int bid   = blockIdx.x;
    int chunk = bid % 16;
    int grp   = bid / 16;        // 0..8
    int dir   = chunk >> 3;
    int jbase = (chunk & 7) * 64;
    const float* wih = dir ? wih_b : wih_f;
    float* xout = dir ? g_xw_b : g_xw_f;

    int w  = tid >> 5, l = tid & 31;
    int ks = l & 3;
    int id = w * 8 + (l >> 2);
    int cg4 = id >> 4;           // 0..3: chars cg4*4..+3 within the 16-group
    int rg  = id & 15;           // 0..15: rows jbase + rg*4..+3

    // weights in regs: 4 rows x 32 k (k-slice ks)
    ulonglong2 wreg[4][8];
#pragma unroll
    for (int r = 0; r < 4; r++)
#pragma unroll
        for (int q = 0; q < 8; q++)
            wreg[r][q] = ((const ulonglong2*)wih)[(size_t)(jbase + rg * 4 + r) * 32 + ks * 8 + q];

    float4 biasv;
    {
        const float4* b1 = (const float4*)(dir ? bih_b : bih_f);
        const float4* b2 = (const float4*)(dir ? bhh_b : bhh_f);
        float4 x = b1[(jbase >> 2) + rg], y = b2[(jbase >> 2) + rg];
        biasv = make_float4(x.x + y.x, x.y + y.y, x.z + y.z, x.w + y.w);
    }

    // preload first group into buffer 0
    ((float4*)esm[0])[tid]       = ((const float4*)emb)[(size_t)grp * 512 + tid];
    ((float4*)esm[0])[tid + 256] = ((const float4*)emb)[(size_t)grp * 512 + tid + 256];
    int pb = 0;

    for (int cg = grp; cg < 1250; cg += 9) {
        __syncthreads();   // buffer pb ready; prior readers of pb^1 done

        int cgn = (cg + 9 < 1250) ? cg + 9 : grp;
        float4 p0 = ((const float4*)emb)[(size_t)cgn * 512 + tid];
        float4 p1 = ((const float4*)emb)[(size_t)cgn * 512 + tid + 256];

        ull acc[4][4];   // [char][row]
#pragma unroll
        for (int c = 0; c < 4; c++)
#pragma unroll
            for (int r = 0; r < 4; r++) acc[c][r] = 0ull;

        const ulonglong2* e2 = (const ulonglong2*)esm[pb];
#pragma unroll
        for (int q = 0; q < 8; q++) {
            ulonglong2 ev[4];
#pragma unroll
            for (int c = 0; c < 4; c++)
                ev[c] = e2[(cg4 * 4 + c) * 32 + ks * 8 + q];
#pragma unroll
            for (int c = 0; c < 4; c++)
#pragma unroll
                for (int r = 0; r < 4; r++) {
                    FMA2(acc[c][r], wreg[r][q].x, ev[c].x);
                    FMA2(acc[c][r], wreg[r][q].y, ev[c].y);
                }
        }

        ((float4*)esm[pb ^ 1])[tid]       = p0;
        ((float4*)esm[pb ^ 1])[tid + 256] = p1;

        float a[4][4];
#pragma unroll
        for (int c = 0; c < 4; c++)
#pragma unroll
            for (int r = 0; r < 4; r++) {
                float v = pair_sum(acc[c][r]);
                v += __shfl_xor_sync(0xffffffffu, v, 1);
                v += __shfl_xor_sync(0xffffffffu, v, 2);
                a[c][r] = v;
            }

        float4 o;
        o.x = a[ks][0] + biasv.x;
        o.y = a[ks][1] + biasv.y;
        o.z = a[ks][2] + biasv.z;
        o.w = a[ks][3] + biasv.w;
        int ch = cg * 16 + cg4 * 4 + ks;
        ((float4*)xout)[(size_t)ch * 128 + (jbase >> 2) + rg] = o;
        pb ^= 1;
    }
}

// =================================================================
// K2: BiLSTM recurrence + fused emission partials.
// R11's exact layout (best measured: k2 = 1.678 ms). Unchanged.
// =================================================================
#define NB 4
// wb 32768 | wl 2560 | hsm 512 | psm 512 | xst 4096 | csm 2048(int)
#define K2_SMEM_FLOATS (32768 + 2560 + 512 + 512 + 4096 + 2048)
#define K2_SMEM_BYTES  (K2_SMEM_FLOATS * 4)

__global__ __launch_bounds__(256, 1) void k2_lstm(
    const int*   __restrict__ chars,
    const float* __restrict__ whh_f, const float* __restrict__ whh_b,
    const float* __restrict__ wlin)
{
    extern __shared__ float sm[];
    float* wb  = sm;            // 32768: [k4][row] float4 of rows 256..511
    float* wl  = sm + 32768;    // 2560 : W_lin direction half
    float* hsm = sm + 35328;    // [nb][128]
    float* psm = sm + 35840;    // [nb][128] i*g exchange
    float* xst = sm + 36352;    // 2 x [nb][512] staged gate inputs
    int*   csm = (int*)(sm + 40448);  // [nb][512] chars

    int tid  = threadIdx.x;
    int bid  = blockIdx.x;
    int dir  = bid >> 6;
    int b0   = (bid & 63) * NB;
    const float* whh = dir ? whh_b : whh_f;
    const float* xw  = dir ? g_xw_b : g_xw_f;
    float* so        = dir ? g_score_b : g_score_f;

    for (int i = tid; i < 32 * 256; i += 256) {
        int k4 = i >> 8, r = i & 255;
        ((float4*)wb)[i] = ((const float4*)whh)[(256 + r) * 32 + k4];
    }
    for (int i = tid; i < TAG * 128; i += 256) {
        int tg = i >> 7, k = i & 127;
        wl[i] = wlin[tg * 256 + dir * 128 + k];
    }
    for (int i = tid; i < NB * 32; i += 256)
        ((float4*)hsm)[i] = make_float4(0.f, 0.f, 0.f, 0.f);
    for (int i = tid; i < NB * 512; i += 256)
        csm[i] = chars[(b0 + (i >> 9)) * TT + (i & 511)];

    ull waU[64];
#pragma unroll
    for (int p = 0; p < 64; p++) waU[p] = ((const ull*)whh)[(size_t)tid * 64 + p];

    {
        int t0 = dir ? TT - 1 : 0;
        int c0 = __ldg(&chars[(b0 + 0) * TT + t0]);
        int c1 = __ldg(&chars[(b0 + 1) * TT + t0]);
        int c2 = __ldg(&chars[(b0 + 2) * TT + t0]);
        int c3 = __ldg(&chars[(b0 + 3) * TT + t0]);
        int cc[4] = {c0, c1, c2, c3};
#pragma unroll
        for (int it = 0; it < 2; it++) {
            int s4 = tid + it * 256;
            int nb = s4 >> 7, q = s4 & 127;
            ((float4*)xst)[s4] = __ldg(&((const float4*)(xw + (size_t)cc[nb] * G4))[q]);
        }
    }
    __syncthreads();

    float creg[NB];
#pragma unroll
    for (int nb = 0; nb < NB; nb++) creg[nb] = 0.f;

    const ulonglong2* wb4 = (const ulonglong2*)wb;
    int cur = 0;

    for (int step = 0; step < TT; step++) {
        int t = dir ? (TT - 1 - step) : step;

        float xa[NB], xb[NB];
        int cid[NB];
#pragma unroll
        for (int nb = 0; nb < NB; nb++) {
            xa[nb]  = xst[cur * 2048 + nb * 512 + tid];
            xb[nb]  = xst[cur * 2048 + nb * 512 + 256 + tid];
            cid[nb] = csm[nb * 512 + t];
        }

        float4 pf0, pf1;
        if (step + 1 < TT) {
            int tn = dir ? (t - 1) : (t + 1);
            int s0 = tid, s1 = tid + 256;
            int cn0 = csm[(s0 >> 7) * 512 + tn];
            int cn1 = csm[(s1 >> 7) * 512 + tn];
            pf0 = __ldg(&((const float4*)(xw + (size_t)cn0 * G4))[s0 & 127]);
            pf1 = __ldg(&((const float4*)(xw + (size_t)cn1 * G4))[s1 & 127]);
        }

        ull accA[NB], accB[NB];
#pragma unroll
        for (int nb = 0; nb < NB; nb++) { accA[nb] = 0ull; accB[nb] = 0ull; }

        const ulonglong2* h4p = (const ulonglong2*)hsm;
#pragma unroll
        for (int k4 = 0; k4 < 32; k4++) {
            ulonglong2 wB = wb4[k4 * 256 + tid];
            ull wA0 = waU[2 * k4], wA1 = waU[2 * k4 + 1];
#pragma unroll
            for (int nb = 0; nb < NB; nb++) {
                ulonglong2 h2 = h4p[nb * 32 + k4];
                FMA2(accA[nb], wA0, h2.x);
                FMA2(accA[nb], wA1, h2.y);
                FMA2(accB[nb], wB.x, h2.x);
                FMA2(accB[nb], wB.y, h2.y);
            }
        }

        float fv[NB], ov[NB];
#pragma unroll
        for (int nb = 0; nb < NB; nb++) {
            float aA = pair_sum(accA[nb]) + xa[nb];
            float aB = pair_sum(accB[nb]) + xb[nb];
            float sA = fast_sigmoid(aA);       // i (tid<128) / f (tid>=128)
            if (tid < 128) {
                psm[nb * 128 + tid] = sA * fast_tanh(aB);   // i*g
            } else {
                fv[nb] = sA;                    // f
                ov[nb] = fast_sigmoid(aB);      // o
            }
        }

        if (step + 1 < TT) {
            ((float4*)(xst + (cur ^ 1) * 2048))[tid]       = pf0;
            ((float4*)(xst + (cur ^ 1) * 2048))[tid + 256] = pf1;
        }
        __syncthreads();

        if (tid >= 128) {
            int u = tid - 128;
#pragma unroll
            for (int nb = 0; nb < NB; nb++) {
                float m  = (cid[nb] > 0) ? 1.f : 0.f;
                float cn = fv[nb] * creg[nb] + psm[nb * 128 + u];
                creg[nb] = cn * m;
                hsm[nb * 128 + u] = ov[nb] * fast_tanh(creg[nb]) * m;
            }
        }
        __syncthreads();

        if (tid < 160) {
            int tg = tid >> 3, p = tid & 7;
#pragma unroll
            for (int nb = 0; nb < NB; nb++) {
                float s = 0.f;
#pragma unroll
                for (int q = 0; q < 4; q++) {
                    float4 w4 = ((const float4*)wl)[tg * 32 + p * 4 + q];
                    float4 hv = ((const float4*)(hsm + nb * 128))[p * 4 + q];
                    s += w4.x * hv.x + w4.y * hv.y + w4.z * hv.z + w4.w * hv.w;
                }
                s += __shfl_down_sync(0xffffffffu, s, 4, 8);
                s += __shfl_down_sync(0xffffffffu, s, 2, 8);
                s += __shfl_down_sync(0xffffffffu, s, 1, 8);
                if (p == 0)
                    so[((size_t)t * BB + (b0 + nb)) * TAG + tg] = s;
            }
        }
        cur ^= 1;
    }
}

// =================================================================
// K3: CRF — factored-lse, register-resident, shfl-only version.
//   lse_k(x[k] + tr[j][k]) = m + log(sum_k exp(x[k]-m) * E[j][k])
// with E[j][k] = exp(tr[j][k]) precomputed per lane (NEG rows -> E=0,
// reproducing the -inf masking semantics exactly).
// grid 128, block 128: warp w -> batch bid*2+(w&1), role w>>1
// (0 = alpha/log-partition, 1 = gold). State in registers; the only
// cross-lane traffic is shfl (no smem ping-pong, no syncwarp).
// =================================================================
__global__ __launch_bounds__(128) void k3_crf(
    const int*   __restrict__ chars,
    const float* __restrict__ tags,
    const float* __restrict__ blin,
    const float* __restrict__ trans)
{
    __shared__ float res[2][2];         // [batch-slot][role]
    const unsigned FULL = 0xffffffffu;

    int tid = threadIdx.x, w = tid >> 5, j = tid & 31;
    int bs = w & 1;           // batch slot 0/1
    int role = w >> 1;        // 0 = alpha, 1 = gold
    int b = blockIdx.x * 2 + bs;
    bool act = (j < TAG);

    // per-lane constants (guarded: j>=20 lanes read nothing)
    float tstj = act ? trans[j * TAG + 1] : 0.f;     // trans[j][START]
    float tspj = act ? trans[2 * TAG + j] : 0.f;     // trans[STOP][j]
    float blj  = act ? blin[j] : 0.f;
    float E[TAG];                                    // exp(trans[j][k])
#pragma unroll
    for (int k = 0; k < TAG; k++)
        E[k] = act ? __expf(trans[j * TAG + k]) : 0.f;

    // sequence length (valid prefix; min length is 256)
    int L = 256;
#pragma unroll
    for (int base = 256; base < 512; base += 32) {
        int c = chars[b * TT + base + j];
        unsigned bal = __ballot_sync(FULL, c > 0);
        L += __popc(bal);
    }

    if (role == 0) {
        // ---------------- alpha (log-partition) warp ----------------
        float alpha = -1e30f;
        if (act) {
            float e0 = g_score_f[(size_t)b * TAG + j] + g_score_b[(size_t)b * TAG + j] + blj;
            alpha = e0 + tstj;
        }

        float nf = 0.f, nbv = 0.f;
        if (act && L > 1) {
            nf  = g_score_f[((size_t)1 * BB + b) * TAG + j];
            nbv = g_score_b[((size_t)1 * BB + b) * TAG + j];
        }

        for (int t = 1; t < L; t++) {
            float emit = nf + nbv + blj;
            if (act && t + 1 < TT) {
                nf  = g_score_f[((size_t)(t + 1) * BB + b) * TAG + j];
                nbv = g_score_b[((size_t)(t + 1) * BB + b) * TAG + j];
            }
            // m = max over active lanes of alpha
            float m = act ? alpha : -1e30f;
#pragma unroll
            for (int o = 16; o; o >>= 1) m = fmaxf(m, __shfl_xor_sync(FULL, m, o));
            float p = act ? __expf(alpha - m) : 0.f;
            float dot = 0.f;
#pragma unroll
            for (int k = 0; k < TAG; k++)
                dot = fmaf(__shfl_sync(FULL, p, k), E[k], dot);
            if (act) alpha = emit + m + __logf(dot);
        }

        // forward_score = lse_k(alpha[k] + trans[STOP][k])
        float av = act ? (alpha + tspj) : -1e30f;
        float m = av;
#pragma unroll
        for (int o = 16; o; o >>= 1) m = fmaxf(m, __shfl_xor_sync(FULL, m, o));
        float p = (av > -1e29f) ? __expf(av - m) : 0.f;
#pragma unroll
        for (int o = 16; o; o >>= 1) p += __shfl_xor_sync(FULL, p, o);
        if (j == 0) res[bs][0] = m + __logf(p);
    } else {
        // ---------------- gold (partial annotation) warp ----------------
        float gold = 0.f, maskp = 0.f;
        if (act) {
            float e0 = g_score_f[(size_t)b * TAG + j] + g_score_b[(size_t)b * TAG + j] + blj;
            float a0 = e0 + tstj;
            float m0 = tags[((size_t)b * TT) * TAG + j];
            gold  = (m0 > 0.f) ? a0 : 0.f;
            maskp = m0;
        }

        float nf = 0.f, nbv = 0.f, nm = 0.f;
        if (act && L > 1) {
            nf  = g_score_f[((size_t)1 * BB + b) * TAG + j];
            nbv = g_score_b[((size_t)1 * BB + b) * TAG + j];
            nm  = tags[((size_t)b * TT + 1) * TAG + j];
        }

        for (int t = 1; t < L; t++) {
            float emit  = nf + nbv + blj;
            float maskc = nm;
            if (act && t + 1 < TT) {
                nf  = g_score_f[((size_t)(t + 1) * BB + b) * TAG + j];
                nbv = g_score_b[((size_t)(t + 1) * BB + b) * TAG + j];
                nm  = tags[((size_t)b * TT + t + 1) * TAG + j];
            }
            // m = max over lanes with maskp>0 of gold
            float m = (maskp > 0.f) ? gold : -1e30f;
#pragma unroll
            for (int o = 16; o; o >>= 1) m = fmaxf(m, __shfl_xor_sync(FULL, m, o));
            float p = (maskp > 0.f) ? __expf(gold - m) : 0.f;
            float dot = 0.f;
#pragma unroll
            for (int k = 0; k < TAG; k++)
                dot = fmaf(__shfl_sync(FULL, p, k), E[k], dot);
            float gv = 0.f;
            if (maskc > 0.f && m > -1e29f)
                gv = emit + m + __logf(dot);
            gold  = act ? gv : 0.f;
            maskp = act ? maskc : 0.f;
        }

        // gold_score = masked lse over tags with gold != 0
        float ms = (act && gold != 0.f) ? 1.f : 0.f;
        float gx = (ms > 0.f) ? (gold + tspj) : -1e30f;
        float gmx = gx, cnt = ms;
#pragma unroll
        for (int o = 16; o; o >>= 1) {
            gmx = fmaxf(gmx, __shfl_xor_sync(FULL, gmx, o));
            cnt += __shfl_xor_sync(FULL, cnt, o);
        }
        float gp = (gx > -1e29f) ? __expf(gx - gmx) : 0.f;
#pragma unroll
        for (int o = 16; o; o >>= 1) gp += __shfl_xor_sync(FULL, gp, o);
        if (j == 0) res[bs][1] = (cnt > 0.f) ? (gmx + __logf(gp)) : 0.f;
    }

    __syncthreads();
    if (tid < 2)
        g_loss[blockIdx.x * 2 + tid] = res[tid][0] - res[tid][1];
}

// =================================================================
// K4: deterministic fixed-order reduction of per-batch losses
// =================================================================
__global__ void k4_reduce(float* out)
{
    int tid = threadIdx.x;
    if (tid < 32) {
        float s = 0.f;
#pragma unroll
        for (int q = 0; q < 8; q++) s += g_loss[tid + 32 * q];
#pragma unroll
        for (int o = 16; o; o >>= 1) s += __shfl_xor_sync(0xffffffffu, s, o);
        if (tid == 0) out[0] = s;
    }
}

// =================================================================
extern "C" void kernel_launch(void* const* d_in, const int* in_sizes, int n_in,
                              void* d_out, int out_size)
{
    const int*   chars = (const int*)  d_in[0];
    const float* tags  = (const float*)d_in[1];
    const float* emb   = (const float*)d_in[2];
    const float* wih_f = (const float*)d_in[3];
    const float* whh_f = (const float*)d_in[4];
    const float* bih_f = (const float*)d_in[5];
    const float* bhh_f = (const float*)d_in[6];
    const float* wih_b = (const float*)d_in[7];
    const float* whh_b = (const float*)d_in[8];
    const float* bih_b = (const float*)d_in[9];
    const float* bhh_b = (const float*)d_in[10];
    const float* wlin  = (const float*)d_in[11];
    const float* blin  = (const float*)d_in[12];
    const float* trans = (const float*)d_in[13];

    cudaFuncSetAttribute(k2_lstm, cudaFuncAttributeMaxDynamicSharedMemorySize, K2_SMEM_BYTES);

    // Launch order puts the NEW k3 in ncu's captured 4th slot:
    // k1, pad, k2, [k3 <- captured], k4
    k1_xw<<<144, 256>>>(emb, wih_f, wih_b, bih_f, bhh_f, bih_b, bhh_b);
    k_pad<<<1, 32>>>();
    k2_lstm<<<128, 256, K2_SMEM_BYTES>>>(chars, whh_f, whh_b, wlin);
    k3_crf<<<128, 128>>>(chars, tags, blin, trans);
    k4_reduce<<<1, 32>>>((float*)d_out);
}

// round 16
// speedup vs baseline: 1.1996x; 1.0139x over previous
#include <cuda_runtime.h>
#include <cuda_bf16.h>
#include <math.h>

// Problem constants
#define BB   256
#define TT   512
#define EE   128
#define HD   128      // per-direction hidden
#define G4   512      // 4*HD
#define TAG  20
#define NCHAR 20000

typedef unsigned long long ull;

// packed f32x2 fma: acc = a*b + acc (elementwise on 2 packed floats)
#define FMA2(acc, a, b) asm("fma.rn.f32x2 %0, %1, %2, %0;" : "+l"(acc) : "l"(a), "l"(b))

__device__ __forceinline__ float pair_sum(ull u) {
    return __uint_as_float((unsigned)u) + __uint_as_float((unsigned)(u >> 32));
}
__device__ __forceinline__ float fast_tanh(float x) {
    float y;
    asm("tanh.approx.f32 %0, %1;" : "=f"(y) : "f"(x));
    return y;
}
__device__ __forceinline__ float fast_sigmoid(float x) {
    return fmaf(0.5f, fast_tanh(0.5f * x), 0.5f);
}

// -------- scratch (device globals; no runtime allocation) --------
__device__ float g_xw_f[(size_t)NCHAR * G4];       // per-char input gates, fwd (41MB)
__device__ float g_xw_b[(size_t)NCHAR * G4];       // per-char input gates, bwd (41MB)
__device__ float g_score_f[(size_t)TT * BB * TAG]; // fwd-direction emission part
__device__ float g_score_b[(size_t)TT * BB * TAG]; // bwd-direction emission part
__device__ float g_loss[BB];

// padding kernel: keeps ncu's fixed capture slot (our 4th launch) on k3
__global__ void k_pad() {}

// =================================================================
// K1: per-character input projection tables (k-split, double-buffered)
// 144 CTAs. Measured-good in R14; unchanged.
// =================================================================
__global__ __launch_bounds__(256, 1) void k1_xw(
    const float* __restrict__ emb,
    const float* __restrict__ wih_f, const float* __restrict__ wih_b,
    const float* __restrict__ bih_f, const float* __restrict__ bhh_f,
    const float* __restrict__ bih_b, const float* __restrict__ bhh_b)
{
    __shared__ float esm[2][16 * 128];   // double-buffered 16-char embedding groups

    int tid   = threadIdx.x;
    int bid   = blockIdx.x;
    int chunk = bid % 16;
    int grp   = bid / 16;        // 0..8
    int dir   = chunk >> 3;
    int jbase = (chunk & 7) * 64;
    const float* wih = dir ? wih_b : wih_f;
    float* xout = dir ? g_xw_b : g_xw_f;

    int w  = tid >> 5, l = tid & 31;
    int ks = l & 3;
    int id = w * 8 + (l >> 2);
    int cg4 = id >> 4;           // 0..3: chars cg4*4..+3 within the 16-group
    int rg  = id & 15;           // 0..15: rows jbase + rg*4..+3

    ulonglong2 wreg[4][8];
#pragma unroll
    for (int r = 0; r < 4; r++)
#pragma unroll
        for (int q = 0; q < 8; q++)
            wreg[r][q] = ((const ulonglong2*)wih)[(size_t)(jbase + rg * 4 + r) * 32 + ks * 8 + q];

    float4 biasv;
    {
        const float4* b1 = (const float4*)(dir ? bih_b : bih_f);
        const float4* b2 = (const float4*)(dir ? bhh_b : bhh_f);
        float4 x = b1[(jbase >> 2) + rg], y = b2[(jbase >> 2) + rg];
        biasv = make_float4(x.x + y.x, x.y + y.y, x.z + y.z, x.w + y.w);
    }

    ((float4*)esm[0])[tid]       = ((const float4*)emb)[(size_t)grp * 512 + tid];
    ((float4*)esm[0])[tid + 256] = ((const float4*)emb)[(size_t)grp * 512 + tid + 256];
    int pb = 0;

    for (int cg = grp; cg < 1250; cg += 9) {
        __syncthreads();

        int cgn = (cg + 9 < 1250) ? cg + 9 : grp;
        float4 p0 = ((const float4*)emb)[(size_t)cgn * 512 + tid];
        float4 p1 = ((const float4*)emb)[(size_t)cgn * 512 + tid + 256];

        ull acc[4][4];   // [char][row]
#pragma unroll
        for (int c = 0; c < 4; c++)
#pragma unroll
            for (int r = 0; r < 4; r++) acc[c][r] = 0ull;

        const ulonglong2* e2 = (const ulonglong2*)esm[pb];
#pragma unroll
        for (int q = 0; q < 8; q++) {
            ulonglong2 ev[4];
#pragma unroll
            for (int c = 0; c < 4; c++)
                ev[c] = e2[(cg4 * 4 + c) * 32 + ks * 8 + q];
#pragma unroll
            for (int c = 0; c < 4; c++)
#pragma unroll
                for (int r = 0; r < 4; r++) {
                    FMA2(acc[c][r], wreg[r][q].x, ev[c].x);
                    FMA2(acc[c][r], wreg[r][q].y, ev[c].y);
                }
        }

        ((float4*)esm[pb ^ 1])[tid]       = p0;
        ((float4*)esm[pb ^ 1])[tid + 256] = p1;

        float a[4][4];
#pragma unroll
        for (int c = 0; c < 4; c++)
#pragma unroll
            for (int r = 0; r < 4; r++) {
                float v = pair_sum(acc[c][r]);
                v += __shfl_xor_sync(0xffffffffu, v, 1);
                v += __shfl_xor_sync(0xffffffffu, v, 2);
                a[c][r] = v;
            }

        float4 o;
        o.x = a[ks][0] + biasv.x;
        o.y = a[ks][1] + biasv.y;
        o.z = a[ks][2] + biasv.z;
        o.w = a[ks][3] + biasv.w;
        int ch = cg * 16 + cg4 * 4 + ks;
        ((float4*)xout)[(size_t)ch * 128 + (jbase >> 2) + rg] = o;
        pb ^= 1;
    }
}

// =================================================================
// K2: BiLSTM recurrence + fused emission partials.
// R11's exact layout (best measured: k2 = 1.678 ms). Unchanged.
// =================================================================
#define NB 4
#define K2_SMEM_FLOATS (32768 + 2560 + 512 + 512 + 4096 + 2048)
#define K2_SMEM_BYTES  (K2_SMEM_FLOATS * 4)

__global__ __launch_bounds__(256, 1) void k2_lstm(
    const int*   __restrict__ chars,
    const float* __restrict__ whh_f, const float* __restrict__ whh_b,
    const float* __restrict__ wlin)
{
    extern __shared__ float sm[];
    float* wb  = sm;            // 32768: [k4][row] float4 of rows 256..511
    float* wl  = sm + 32768;    // 2560 : W_lin direction half
    float* hsm = sm + 35328;    // [nb][128]
    float* psm = sm + 35840;    // [nb][128] i*g exchange
    float* xst = sm + 36352;    // 2 x [nb][512] staged gate inputs
    int*   csm = (int*)(sm + 40448);  // [nb][512] chars

    int tid  = threadIdx.x;
    int bid  = blockIdx.x;
    int dir  = bid >> 6;
    int b0   = (bid & 63) * NB;
    const float* whh = dir ? whh_b : whh_f;
    const float* xw  = dir ? g_xw_b : g_xw_f;
    float* so        = dir ? g_score_b : g_score_f;

    for (int i = tid; i < 32 * 256; i += 256) {
        int k4 = i >> 8, r = i & 255;
        ((float4*)wb)[i] = ((const float4*)whh)[(256 + r) * 32 + k4];
    }
    for (int i = tid; i < TAG * 128; i += 256) {
        int tg = i >> 7, k = i & 127;
        wl[i] = wlin[tg * 256 + dir * 128 + k];
    }
    for (int i = tid; i < NB * 32; i += 256)
        ((float4*)hsm)[i] = make_float4(0.f, 0.f, 0.f, 0.f);
    for (int i = tid; i < NB * 512; i += 256)
        csm[i] = chars[(b0 + (i >> 9)) * TT + (i & 511)];

    ull waU[64];
#pragma unroll
    for (int p = 0; p < 64; p++) waU[p] = ((const ull*)whh)[(size_t)tid * 64 + p];

    {
        int t0 = dir ? TT - 1 : 0;
        int c0 = __ldg(&chars[(b0 + 0) * TT + t0]);
        int c1 = __ldg(&chars[(b0 + 1) * TT + t0]);
        int c2 = __ldg(&chars[(b0 + 2) * TT + t0]);
        int c3 = __ldg(&chars[(b0 + 3) * TT + t0]);
        int cc[4] = {c0, c1, c2, c3};
#pragma unroll
        for (int it = 0; it < 2; it++) {
            int s4 = tid + it * 256;
            int nb = s4 >> 7, q = s4 & 127;
            ((float4*)xst)[s4] = __ldg(&((const float4*)(xw + (size_t)cc[nb] * G4))[q]);
        }
    }
    __syncthreads();

    float creg[NB];
#pragma unroll
    for (int nb = 0; nb < NB; nb++) creg[nb] = 0.f;

    const ulonglong2* wb4 = (const ulonglong2*)wb;
    int cur = 0;

    for (int step = 0; step < TT; step++) {
        int t = dir ? (TT - 1 - step) : step;

        float xa[NB], xb[NB];
        int cid[NB];
#pragma unroll
        for (int nb = 0; nb < NB; nb++) {
            xa[nb]  = xst[cur * 2048 + nb * 512 + tid];
            xb[nb]  = xst[cur * 2048 + nb * 512 + 256 + tid];
            cid[nb] = csm[nb * 512 + t];
        }

        float4 pf0, pf1;
        if (step + 1 < TT) {
            int tn = dir ? (t - 1) : (t + 1);
            int s0 = tid, s1 = tid + 256;
            int cn0 = csm[(s0 >> 7) * 512 + tn];
            int cn1 = csm[(s1 >> 7) * 512 + tn];
            pf0 = __ldg(&((const float4*)(xw + (size_t)cn0 * G4))[s0 & 127]);
            pf1 = __ldg(&((const float4*)(xw + (size_t)cn1 * G4))[s1 & 127]);
        }

        ull accA[NB], accB[NB];
#pragma unroll
        for (int nb = 0; nb < NB; nb++) { accA[nb] = 0ull; accB[nb] = 0ull; }

        const ulonglong2* h4p = (const ulonglong2*)hsm;
#pragma unroll
        for (int k4 = 0; k4 < 32; k4++) {
            ulonglong2 wB = wb4[k4 * 256 + tid];
            ull wA0 = waU[2 * k4], wA1 = waU[2 * k4 + 1];
#pragma unroll
            for (int nb = 0; nb < NB; nb++) {
                ulonglong2 h2 = h4p[nb * 32 + k4];
                FMA2(accA[nb], wA0, h2.x);
                FMA2(accA[nb], wA1, h2.y);
                FMA2(accB[nb], wB.x, h2.x);
                FMA2(accB[nb], wB.y, h2.y);
            }
        }

        float fv[NB], ov[NB];
#pragma unroll
        for (int nb = 0; nb < NB; nb++) {
            float aA = pair_sum(accA[nb]) + xa[nb];
            float aB = pair_sum(accB[nb]) + xb[nb];
            float sA = fast_sigmoid(aA);       // i (tid<128) / f (tid>=128)
            if (tid < 128) {
                psm[nb * 128 + tid] = sA * fast_tanh(aB);   // i*g
            } else {
                fv[nb] = sA;                    // f
                ov[nb] = fast_sigmoid(aB);      // o
            }
        }

        if (step + 1 < TT) {
            ((float4*)(xst + (cur ^ 1) * 2048))[tid]       = pf0;
            ((float4*)(xst + (cur ^ 1) * 2048))[tid + 256] = pf1;
        }
        __syncthreads();

        if (tid >= 128) {
            int u = tid - 128;
#pragma unroll
            for (int nb = 0; nb < NB; nb++) {
                float m  = (cid[nb] > 0) ? 1.f : 0.f;
                float cn = fv[nb] * creg[nb] + psm[nb * 128 + u];
                creg[nb] = cn * m;
                hsm[nb * 128 + u] = ov[nb] * fast_tanh(creg[nb]) * m;
            }
        }
        __syncthreads();

        if (tid < 160) {
            int tg = tid >> 3, p = tid & 7;
#pragma unroll
            for (int nb = 0; nb < NB; nb++) {
                float s = 0.f;
#pragma unroll
                for (int q = 0; q < 4; q++) {
                    float4 w4 = ((const float4*)wl)[tg * 32 + p * 4 + q];
                    float4 hv = ((const float4*)(hsm + nb * 128))[p * 4 + q];
                    s += w4.x * hv.x + w4.y * hv.y + w4.z * hv.z + w4.w * hv.w;
                }
                s += __shfl_down_sync(0xffffffffu, s, 4, 8);
                s += __shfl_down_sync(0xffffffffu, s, 2, 8);
                s += __shfl_down_sync(0xffffffffu, s, 1, 8);
                if (p == 0)
                    so[((size_t)t * BB + (b0 + nb)) * TAG + tg] = s;
            }
        }
        cur ^= 1;
    }
}

// =================================================================
// K3: CRF — LINEAR-SPACE scan with deferred renormalization.
// State v_k = exp(alpha_k - logC); per step v'_j = e^emit_j * dot,
// dot = sum_k v_k * E[j][k], E = exp(trans) (NEG rows -> 0 exactly).
// Max-allreduce + log only every 2nd step (renorm). Emissions read
// through a depth-4 rotating register ring (hides L2 latency).
// grid 128, block 128: warp w -> batch bid*2+(w&1), role w>>1.
// =================================================================
__global__ __launch_bounds__(128) void k3_crf(
    const int*   __restrict__ chars,
    const float* __restrict__ tags,
    const float* __restrict__ blin,
    const float* __restrict__ trans)
{
    __shared__ float res[2][2];         // [batch-slot][role]
    const unsigned FULL = 0xffffffffu;

    int tid = threadIdx.x, w = tid >> 5, j = tid & 31;
    int bs = w & 1;           // batch slot 0/1
    int role = w >> 1;        // 0 = alpha, 1 = gold
    int b = blockIdx.x * 2 + bs;
    bool act = (j < TAG);

    float tstj = act ? trans[j * TAG + 1] : 0.f;     // trans[j][START]
    float blj  = act ? blin[j] : 0.f;
    float Esp  = act ? __expf(trans[2 * TAG + j]) : 0.f;  // exp(trans[STOP][j]); NEG->0
    float E[TAG];                                    // exp(trans[j][k]); NEG->0
#pragma unroll
    for (int k = 0; k < TAG; k++)
        E[k] = act ? __expf(trans[j * TAG + k]) : 0.f;

    // sequence length (valid prefix; min length is 256)
    int L = 256;
#pragma unroll
    for (int base = 256; base < 512; base += 32) {
        int c = chars[b * TT + base + j];
        unsigned bal = __ballot_sync(FULL, c > 0);
        L += __popc(bal);
    }

    if (role == 0) {
        // ---------------- alpha (log-partition) warp ----------------
        float a0 = -1e30f;
        if (act)
            a0 = g_score_f[(size_t)b * TAG + j] + g_score_b[(size_t)b * TAG + j] + blj + tstj;
        float m = a0;
#pragma unroll
        for (int o = 16; o; o >>= 1) m = fmaxf(m, __shfl_xor_sync(FULL, m, o));
        float v = act ? __expf(a0 - m) : 0.f;
        float logC = m;

        // depth-4 emission ring (rotating registers)
        float f0 = 0, f1 = 0, f2 = 0, f3 = 0, g0 = 0, g1 = 0, g2 = 0, g3 = 0;
        if (act) {
            f0 = g_score_f[((size_t)1 * BB + b) * TAG + j]; g0 = g_score_b[((size_t)1 * BB + b) * TAG + j];
            f1 = g_score_f[((size_t)2 * BB + b) * TAG + j]; g1 = g_score_b[((size_t)2 * BB + b) * TAG + j];
            f2 = g_score_f[((size_t)3 * BB + b) * TAG + j]; g2 = g_score_b[((size_t)3 * BB + b) * TAG + j];
            f3 = g_score_f[((size_t)4 * BB + b) * TAG + j]; g3 = g_score_b[((size_t)4 * BB + b) * TAG + j];
        }

        for (int t = 1; t < L; t++) {
            float emit = f0 + g0 + blj;
            // rotate ring; load t+4 (clamped)
            f0 = f1; g0 = g1; f1 = f2; g1 = g2; f2 = f3; g2 = g3;
            int tl = (t + 4 < TT) ? t + 4 : TT - 1;
            if (act) {
                f3 = g_score_f[((size_t)tl * BB + b) * TAG + j];
                g3 = g_score_b[((size_t)tl * BB + b) * TAG + j];
            }
            float eE = __expf(emit);   // off-chain
            float d0 = 0.f, d1 = 0.f, d2 = 0.f, d3 = 0.f;
#pragma unroll
            for (int k = 0; k < TAG; k += 4) {
                d0 = fmaf(__shfl_sync(FULL, v, k + 0), E[k + 0], d0);
                d1 = fmaf(__shfl_sync(FULL, v, k + 1), E[k + 1], d1);
                d2 = fmaf(__shfl_sync(FULL, v, k + 2), E[k + 2], d2);
                d3 = fmaf(__shfl_sync(FULL, v, k + 3), E[k + 3], d3);
            }
            float dot = (d0 + d1) + (d2 + d3);
            v = act ? (eE * dot) : 0.f;
            if ((t & 1) == 0) {       // renorm every 2nd step
                float mx = v;
#pragma unroll
                for (int o = 16; o; o >>= 1) mx = fmaxf(mx, __shfl_xor_sync(FULL, mx, o));
                if (mx > 0.f) {
                    v *= __fdividef(1.f, mx);
                    logC += __logf(mx);
                }
            }
        }

        // final renorm + stop-transition sum
        float mx = v;
#pragma unroll
        for (int o = 16; o; o >>= 1) mx = fmaxf(mx, __shfl_xor_sync(FULL, mx, o));
        v *= __fdividef(1.f, mx);
        logC += __logf(mx);
        float s = v * Esp;
#pragma unroll
        for (int o = 16; o; o >>= 1) s += __shfl_xor_sync(FULL, s, o);
        if (j == 0) res[bs][0] = logC + __logf(s);
    } else {
        // ---------------- gold (partial annotation) warp ----------------
        float m0 = act ? tags[((size_t)b * TT) * TAG + j] : 0.f;
        float a0 = -1e30f;
        if (act && m0 > 0.f)
            a0 = g_score_f[(size_t)b * TAG + j] + g_score_b[(size_t)b * TAG + j] + blj + tstj;
        float m = a0;
#pragma unroll
        for (int o = 16; o; o >>= 1) m = fmaxf(m, __shfl_xor_sync(FULL, m, o));
        float v = (act && m0 > 0.f) ? __expf(a0 - m) : 0.f;
        float logC = m;

        float f0 = 0, f1 = 0, f2 = 0, f3 = 0, g0 = 0, g1 = 0, g2 = 0, g3 = 0;
        float t0 = 0, t1 = 0, t2 = 0, t3 = 0;
        if (act) {
            f0 = g_score_f[((size_t)1 * BB + b) * TAG + j]; g0 = g_score_b[((size_t)1 * BB + b) * TAG + j];
            f1 = g_score_f[((size_t)2 * BB + b) * TAG + j]; g1 = g_score_b[((size_t)2 * BB + b) * TAG + j];
            f2 = g_score_f[((size_t)3 * BB + b) * TAG + j]; g2 = g_score_b[((size_t)3 * BB + b) * TAG + j];
            f3 = g_score_f[((size_t)4 * BB + b) * TAG + j]; g3 = g_score_b[((size_t)4 * BB + b) * TAG + j];
            t0 = tags[((size_t)b * TT + 1) * TAG + j];
            t1 = tags[((size_t)b * TT + 2) * TAG + j];
            t2 = tags[((size_t)b * TT + 3) * TAG + j];
            t3 = tags[((size_t)b * TT + 4) * TAG + j];
        }

        for (int t = 1; t < L; t++) {
            float emit  = f0 + g0 + blj;
            float maskc = t0;
            f0 = f1; g0 = g1; t0 = t1;
            f1 = f2; g1 = g2; t1 = t2;
            f2 = f3; g2 = g3; t2 = t3;
            int tl = (t + 4 < TT) ? t + 4 : TT - 1;
            if (act) {
                f3 = g_score_f[((size_t)tl * BB + b) * TAG + j];
                g3 = g_score_b[((size_t)tl * BB + b) * TAG + j];
                t3 = tags[((size_t)b * TT + tl) * TAG + j];
            }
            float eE = __expf(emit);
            float d0 = 0.f, d1 = 0.f, d2 = 0.f, d3 = 0.f;
#pragma unroll
            for (int k = 0; k < TAG; k += 4) {
                d0 = fmaf(__shfl_sync(FULL, v, k + 0), E[k + 0], d0);
                d1 = fmaf(__shfl_sync(FULL, v, k + 1), E[k + 1], d1);
                d2 = fmaf(__shfl_sync(FULL, v, k + 2), E[k + 2], d2);
                d3 = fmaf(__shfl_sync(FULL, v, k + 3), E[k + 3], d3);
            }
            float dot = (d0 + d1) + (d2 + d3);
            v = (act && maskc > 0.f) ? (eE * dot) : 0.f;
            if ((t & 1) == 0) {
                float mx = v;
#pragma unroll
                for (int o = 16; o; o >>= 1) mx = fmaxf(mx, __shfl_xor_sync(FULL, mx, o));
                if (mx > 0.f) {
                    v *= __fdividef(1.f, mx);
                    logC += __logf(mx);
                }
            }
        }

        // final renorm + stop-transition masked sum
        float mx = v;
#pragma unroll
        for (int o = 16; o; o >>= 1) mx = fmaxf(mx, __shfl_xor_sync(FULL, mx, o));
        if (mx > 0.f) {
            v *= __fdividef(1.f, mx);
            logC += __logf(mx);
        }
        float s = v * Esp;
#pragma unroll
        for (int o = 16; o; o >>= 1) s += __shfl_xor_sync(FULL, s, o);
        if (j == 0) res[bs][1] = (s > 0.f) ? (logC + __logf(s)) : 0.f;
    }

    __syncthreads();
    if (tid < 2)
        g_loss[blockIdx.x * 2 + tid] = res[tid][0] - res[tid][1];
}

// =================================================================
// K4: deterministic fixed-order reduction of per-batch losses
// =================================================================
__global__ void k4_reduce(float* out)
{
    int tid = threadIdx.x;
    if (tid < 32) {
        float s = 0.f;
#pragma unroll
        for (int q = 0; q < 8; q++) s += g_loss[tid + 32 * q];
#pragma unroll
        for (int o = 16; o; o >>= 1) s += __shfl_xor_sync(0xffffffffu, s, o);
        if (tid == 0) out[0] = s;
    }
}

// =================================================================
extern "C" void kernel_launch(void* const* d_in, const int* in_sizes, int n_in,
                              void* d_out, int out_size)
{
    const int*   chars = (const int*)  d_in[0];
    const float* tags  = (const float*)d_in[1];
    const float* emb   = (const float*)d_in[2];
    const float* wih_f = (const float*)d_in[3];
    const float* whh_f = (const float*)d_in[4];
    const float* bih_f = (const float*)d_in[5];
    const float* bhh_f = (const float*)d_in[6];
    const float* wih_b = (const float*)d_in[7];
    const float* whh_b = (const float*)d_in[8];
    const float* bih_b = (const float*)d_in[9];
    const float* bhh_b = (const float*)d_in[10];
    const float* wlin  = (const float*)d_in[11];
    const float* blin  = (const float*)d_in[12];
    const float* trans = (const float*)d_in[13];

    cudaFuncSetAttribute(k2_lstm, cudaFuncAttributeMaxDynamicSharedMemorySize, K2_SMEM_BYTES);

    // Launch order puts k3 in ncu's captured 4th slot:
    // k1, pad, k2, [k3 <- captured], k4
    k1_xw<<<144, 256>>>(emb, wih_f, wih_b, bih_f, bhh_f, bih_b, bhh_b);
    k_pad<<<1, 32>>>();
    k2_lstm<<<128, 256, K2_SMEM_BYTES>>>(chars, whh_f, whh_b, wlin);
    k3_crf<<<128, 128>>>(chars, tags, blin, trans);
    k4_reduce<<<1, 32>>>((float*)d_out);
}

// round 17
// speedup vs baseline: 1.2735x; 1.0616x over previous
#include <cuda_runtime.h>
#include <cuda_bf16.h>
#include <math.h>

// Problem constants
#define BB   256
#define TT   512
#define EE   128
#define HD   128      // per-direction hidden
#define G4   512      // 4*HD
#define TAG  20
#define NCHAR 20000

typedef unsigned long long ull;

// packed f32x2 fma: acc = a*b + acc (elementwise on 2 packed floats)
#define FMA2(acc, a, b) asm("fma.rn.f32x2 %0, %1, %2, %0;" : "+l"(acc) : "l"(a), "l"(b))

__device__ __forceinline__ float pair_sum(ull u) {
    return __uint_as_float((unsigned)u) + __uint_as_float((unsigned)(u >> 32));
}
__device__ __forceinline__ float fast_tanh(float x) {
    float y;
    asm("tanh.approx.f32 %0, %1;" : "=f"(y) : "f"(x));
    return y;
}
__device__ __forceinline__ float fast_sigmoid(float x) {
    return fmaf(0.5f, fast_tanh(0.5f * x), 0.5f);
}

// -------- scratch (device globals; no runtime allocation) --------
__device__ float g_xw_f[(size_t)NCHAR * G4];       // per-char input gates, fwd (41MB)
__device__ float g_xw_b[(size_t)NCHAR * G4];       // per-char input gates, bwd (41MB)
__device__ float g_score_f[(size_t)TT * BB * TAG]; // fwd-direction emission part
__device__ float g_score_b[(size_t)TT * BB * TAG]; // bwd-direction emission part
__device__ float g_loss[BB];

// padding kernel: steers ncu's fixed capture slot (our 4th launch) onto k2
__global__ void k_pad() {}

// =================================================================
// K1: per-character input projection tables (k-split, double-buffered)
// 144 CTAs. Measured-good in R14; unchanged.
// =================================================================
__global__ __launch_bounds__(256, 1) void k1_xw(
    const float* __restrict__ emb,
    const float* __restrict__ wih_f, const float* __restrict__ wih_b,
    const float* __restrict__ bih_f, const float* __restrict__ bhh_f,
    const float* __restrict__ bih_b, const float* __restrict__ bhh_b)
{
    __shared__ float esm[2][16 * 128];   // double-buffered 16-char embedding groups

    int tid   = threadIdx.x;
    int bid   = blockIdx.x;
    int chunk = bid % 16;
    int grp   = bid / 16;        // 0..8
    int dir   = chunk >> 3;
    int jbase = (chunk & 7) * 64;
    const float* wih = dir ? wih_b : wih_f;
    float* xout = dir ? g_xw_b : g_xw_f;

    int w  = tid >> 5, l = tid & 31;
    int ks = l & 3;
    int id = w * 8 + (l >> 2);
    int cg4 = id >> 4;           // 0..3: chars cg4*4..+3 within the 16-group
    int rg  = id & 15;           // 0..15: rows jbase + rg*4..+3

    ulonglong2 wreg[4][8];
#pragma unroll
    for (int r = 0; r < 4; r++)
#pragma unroll
        for (int q = 0; q < 8; q++)
            wreg[r][q] = ((const ulonglong2*)wih)[(size_t)(jbase + rg * 4 + r) * 32 + ks * 8 + q];

    float4 biasv;
    {
        const float4* b1 = (const float4*)(dir ? bih_b : bih_f);
        const float4* b2 = (const float4*)(dir ? bhh_b : bhh_f);
        float4 x = b1[(jbase >> 2) + rg], y = b2[(jbase >> 2) + rg];
        biasv = make_float4(x.x + y.x, x.y + y.y, x.z + y.z, x.w + y.w);
    }

    ((float4*)esm[0])[tid]       = ((const float4*)emb)[(size_t)grp * 512 + tid];
    ((float4*)esm[0])[tid + 256] = ((const float4*)emb)[(size_t)grp * 512 + tid + 256];
    int pb = 0;

    for (int cg = grp; cg < 1250; cg += 9) {
        __syncthreads();

        int cgn = (cg + 9 < 1250) ? cg + 9 : grp;
        float4 p0 = ((const float4*)emb)[(size_t)cgn * 512 + tid];
        float4 p1 = ((const float4*)emb)[(size_t)cgn * 512 + tid + 256];

        ull acc[4][4];   // [char][row]
#pragma unroll
        for (int c = 0; c < 4; c++)
#pragma unroll
            for (int r = 0; r < 4; r++) acc[c][r] = 0ull;

        const ulonglong2* e2 = (const ulonglong2*)esm[pb];
#pragma unroll
        for (int q = 0; q < 8; q++) {
            ulonglong2 ev[4];
#pragma unroll
            for (int c = 0; c < 4; c++)
                ev[c] = e2[(cg4 * 4 + c) * 32 + ks * 8 + q];
#pragma unroll
            for (int c = 0; c < 4; c++)
#pragma unroll
                for (int r = 0; r < 4; r++) {
                    FMA2(acc[c][r], wreg[r][q].x, ev[c].x);
                    FMA2(acc[c][r], wreg[r][q].y, ev[c].y);
                }
        }

        ((float4*)esm[pb ^ 1])[tid]       = p0;
        ((float4*)esm[pb ^ 1])[tid + 256] = p1;

        float a[4][4];
#pragma unroll
        for (int c = 0; c < 4; c++)
#pragma unroll
            for (int r = 0; r < 4; r++) {
                float v = pair_sum(acc[c][r]);
                v += __shfl_xor_sync(0xffffffffu, v, 1);
                v += __shfl_xor_sync(0xffffffffu, v, 2);
                a[c][r] = v;
            }

        float4 o;
        o.x = a[ks][0] + biasv.x;
        o.y = a[ks][1] + biasv.y;
        o.z = a[ks][2] + biasv.z;
        o.w = a[ks][3] + biasv.w;
        int ch = cg * 16 + cg4 * 4 + ks;
        ((float4*)xout)[(size_t)ch * 128 + (jbase >> 2) + rg] = o;
        pb ^= 1;
    }
}

// =================================================================
// K2: BiLSTM recurrence + fused emission partials.
// SINGLE-BARRIER variant of the R11 layout:
//  - lane-paired gate ownership: role = l&1, u = w*16 + (l>>1);
//    role 0 owns rows (u [i], 256+u [g]); role 1 owns (128+u [f],
//    384+u [o]). i*g moves to the partner lane via ONE shfl_xor(1).
//  - ping-pong hsm: h_t written to buffer cur^1 while gemm reads cur,
//    so only one __syncthreads per step; emission overlaps next gemm.
// grid 128: bid<64 fwd batches 4*bid..+3; bid>=64 bwd.
// =================================================================
#define NB 4
// wb 32768 | wl 2560 | hsm 1024 (2 bufs) | xst 4096 | csm 2048(int)
#define K2_SMEM_FLOATS (32768 + 2560 + 1024 + 4096 + 2048)
#define K2_SMEM_BYTES  (K2_SMEM_FLOATS * 4)

__global__ __launch_bounds__(256, 1) void k2_lstm(
    const int*   __restrict__ chars,
    const float* __restrict__ whh_f, const float* __restrict__ whh_b,
    const float* __restrict__ wlin)
{
    extern __shared__ float sm[];
    float* wb  = sm;            // 32768: [k4][reader-tid] float4 smem weight bank
    float* wl  = sm + 32768;    // 2560 : W_lin direction half
    float* hsm = sm + 35328;    // 2 x [nb][128] ping-pong h
    float* xst = sm + 36352;    // 2 x [nb][512] staged gate inputs
    int*   csm = (int*)(sm + 40448);  // [nb][512] chars

    int tid  = threadIdx.x;
    int bid  = blockIdx.x;
    int dir  = bid >> 6;
    int b0   = (bid & 63) * NB;
    const float* whh = dir ? whh_b : whh_f;
    const float* xw  = dir ? g_xw_b : g_xw_f;
    float* so        = dir ? g_score_b : g_score_f;

    int w = tid >> 5, l = tid & 31;
    int role = l & 1;                 // 0: i,g rows ; 1: f,o rows
    int u    = w * 16 + (l >> 1);     // unit 0..127
    int regRow  = role * 128 + u;     // i_u or f_u
    int smemRowL = role * 128 + u;    // local row within 256..511: g_u or o_u

    // smem weight bank in READER order: slot i = k4*256 + tt holds
    // row 256 + (tt&1)*128 + (tt>>5)*16 + ((tt&31)>>1)  -> conflict-free reads
    for (int i = tid; i < 32 * 256; i += 256) {
        int k4 = i >> 8, tt = i & 255;
        int rr = 256 + (tt & 1) * 128 + (tt >> 5) * 16 + ((tt & 31) >> 1);
        ((float4*)wb)[i] = ((const float4*)whh)[(size_t)rr * 32 + k4];
    }
    for (int i = tid; i < TAG * 128; i += 256) {
        int tg = i >> 7, k = i & 127;
        wl[i] = wlin[tg * 256 + dir * 128 + k];
    }
    for (int i = tid; i < 2 * NB * 32; i += 256)
        ((float4*)hsm)[i] = make_float4(0.f, 0.f, 0.f, 0.f);
    for (int i = tid; i < NB * 512; i += 256)
        csm[i] = chars[(b0 + (i >> 9)) * TT + (i & 511)];

    // register weights for regRow, packed as 64 k-pairs
    ull waU[64];
#pragma unroll
    for (int p = 0; p < 64; p++) waU[p] = ((const ull*)whh)[(size_t)regRow * 64 + p];

    // initial stage: xstage[0] for the first timestep
    {
        int t0 = dir ? TT - 1 : 0;
        int c0 = __ldg(&chars[(b0 + 0) * TT + t0]);
        int c1 = __ldg(&chars[(b0 + 1) * TT + t0]);
        int c2 = __ldg(&chars[(b0 + 2) * TT + t0]);
        int c3 = __ldg(&chars[(b0 + 3) * TT + t0]);
        int cc[4] = {c0, c1, c2, c3};
#pragma unroll
        for (int it = 0; it < 2; it++) {
            int s4 = tid + it * 256;        // float4 slot 0..511
            int nb = s4 >> 7, q = s4 & 127;
            ((float4*)xst)[s4] = __ldg(&((const float4*)(xw + (size_t)cc[nb] * G4))[q]);
        }
    }
    __syncthreads();

    float creg[NB];                     // cell state (meaningful on role-1 lanes)
#pragma unroll
    for (int nb = 0; nb < NB; nb++) creg[nb] = 0.f;

    const ulonglong2* wb4 = (const ulonglong2*)wb;
    int cur = 0;

    for (int step = 0; step < TT; step++) {
        int t = dir ? (TT - 1 - step) : step;

        // gate inputs for this thread's two rows + masks from smem
        float xa[NB], xb[NB];
        int cid[NB];
#pragma unroll
        for (int nb = 0; nb < NB; nb++) {
            xa[nb]  = xst[cur * 2048 + nb * 512 + regRow];
            xb[nb]  = xst[cur * 2048 + nb * 512 + 256 + smemRowL];
            cid[nb] = csm[nb * 512 + t];
        }

        // prefetch next step's gate inputs (coalesced float4 LDG)
        float4 pf0, pf1;
        if (step + 1 < TT) {
            int tn = dir ? (t - 1) : (t + 1);
            int s0 = tid, s1 = tid + 256;
            int cn0 = csm[(s0 >> 7) * 512 + tn];
            int cn1 = csm[(s1 >> 7) * 512 + tn];
            pf0 = __ldg(&((const float4*)(xw + (size_t)cn0 * G4))[s0 & 127]);
            pf1 = __ldg(&((const float4*)(xw + (size_t)cn1 * G4))[s1 & 127]);
        }

        ull accA[NB], accB[NB];
#pragma unroll
        for (int nb = 0; nb < NB; nb++) { accA[nb] = 0ull; accB[nb] = 0ull; }

        const ulonglong2* h4p = (const ulonglong2*)(hsm + cur * 512);
#pragma unroll
        for (int k4 = 0; k4 < 32; k4++) {
            ulonglong2 wB = wb4[k4 * 256 + tid];
            ull wA0 = waU[2 * k4], wA1 = waU[2 * k4 + 1];
#pragma unroll
            for (int nb = 0; nb < NB; nb++) {
                ulonglong2 h2 = h4p[nb * 32 + k4];
                FMA2(accA[nb], wA0, h2.x);
                FMA2(accA[nb], wA1, h2.y);
                FMA2(accB[nb], wB.x, h2.x);
                FMA2(accB[nb], wB.y, h2.y);
            }
        }

        // activations + lane-pair exchange + c/h update (no barrier)
#pragma unroll
        for (int nb = 0; nb < NB; nb++) {
            float aA = pair_sum(accA[nb]) + xa[nb];
            float aB = pair_sum(accB[nb]) + xb[nb];
            float sA = fast_sigmoid(aA);          // i (role0) / f (role1)
            float send, sO = 0.f;
            if (role == 0) {
                send = sA * fast_tanh(aB);        // i*g
            } else {
                send = 0.f;
                sO = fast_sigmoid(aB);            // o
            }
            float pp = __shfl_xor_sync(0xffffffffu, send, 1);  // role1 gets i*g
            if (role == 1) {
                float m  = (cid[nb] > 0) ? 1.f : 0.f;
                float cn = (sA * creg[nb] + pp) * m;
                creg[nb] = cn;
                hsm[(cur ^ 1) * 512 + nb * 128 + u] = sO * fast_tanh(cn) * m;
            }
        }

        // commit prefetch to the other stage buffer before the barrier
        if (step + 1 < TT) {
            ((float4*)(xst + (cur ^ 1) * 2048))[tid]       = pf0;
            ((float4*)(xst + (cur ^ 1) * 2048))[tid + 256] = pf1;
        }
        __syncthreads();   // h_t published; next gemm + emission both read cur^1

        // emission partials: 20 tags x 8 k-chunks over warps 0..4 (reads h_t)
        if (tid < 160) {
            int tg = tid >> 3, p = tid & 7;
            const float4* hb = (const float4*)(hsm + (cur ^ 1) * 512);
#pragma unroll
            for (int nb = 0; nb < NB; nb++) {
                float s = 0.f;
#pragma unroll
                for (int q = 0; q < 4; q++) {
                    float4 w4 = ((const float4*)wl)[tg * 32 + p * 4 + q];
                    float4 hv = hb[nb * 32 + p * 4 + q];
                    s += w4.x * hv.x + w4.y * hv.y + w4.z * hv.z + w4.w * hv.w;
                }
                s += __shfl_down_sync(0xffffffffu, s, 4, 8);
                s += __shfl_down_sync(0xffffffffu, s, 2, 8);
                s += __shfl_down_sync(0xffffffffu, s, 1, 8);
                if (p == 0)
                    so[((size_t)t * BB + (b0 + nb)) * TAG + tg] = s;
            }
        }
        cur ^= 1;
    }
}

// =================================================================
// K3: CRF — linear-space scan (R16 passing version; unchanged)
// =================================================================
__global__ __launch_bounds__(128) void k3_crf(
    const int*   __restrict__ chars,
    const float* __restrict__ tags,
    const float* __restrict__ blin,
    const float* __restrict__ trans)
{
    __shared__ float res[2][2];         // [batch-slot][role]
    const unsigned FULL = 0xffffffffu;

    int tid = threadIdx.x, w = tid >> 5, j = tid & 31;
    int bs = w & 1;           // batch slot 0/1
    int role = w >> 1;        // 0 = alpha, 1 = gold
    int b = blockIdx.x * 2 + bs;
    bool act = (j < TAG);

    float tstj = act ? trans[j * TAG + 1] : 0.f;     // trans[j][START]
    float blj  = act ? blin[j] : 0.f;
    float Esp  = act ? __expf(trans[2 * TAG + j]) : 0.f;  // exp(trans[STOP][j])
    float E[TAG];
#pragma unroll
    for (int k = 0; k < TAG; k++)
        E[k] = act ? __expf(trans[j * TAG + k]) : 0.f;

    int L = 256;
#pragma unroll
    for (int base = 256; base < 512; base += 32) {
        int c = chars[b * TT + base + j];
        unsigned bal = __ballot_sync(FULL, c > 0);
        L += __popc(bal);
    }

    if (role == 0) {
        float a0 = -1e30f;
        if (act)
            a0 = g_score_f[(size_t)b * TAG + j] + g_score_b[(size_t)b * TAG + j] + blj + tstj;
        float m = a0;
#pragma unroll
        for (int o = 16; o; o >>= 1) m = fmaxf(m, __shfl_xor_sync(FULL, m, o));
        float v = act ? __expf(a0 - m) : 0.f;
        float logC = m;

        float f0 = 0, f1 = 0, f2 = 0, f3 = 0, g0 = 0, g1 = 0, g2 = 0, g3 = 0;
        if (act) {
            f0 = g_score_f[((size_t)1 * BB + b) * TAG + j]; g0 = g_score_b[((size_t)1 * BB + b) * TAG + j];
            f1 = g_score_f[((size_t)2 * BB + b) * TAG + j]; g1 = g_score_b[((size_t)2 * BB + b) * TAG + j];
            f2 = g_score_f[((size_t)3 * BB + b) * TAG + j]; g2 = g_score_b[((size_t)3 * BB + b) * TAG + j];
            f3 = g_score_f[((size_t)4 * BB + b) * TAG + j]; g3 = g_score_b[((size_t)4 * BB + b) * TAG + j];
        }

        for (int t = 1; t < L; t++) {
            float emit = f0 + g0 + blj;
            f0 = f1; g0 = g1; f1 = f2; g1 = g2; f2 = f3; g2 = g3;
            int tl = (t + 4 < TT) ? t + 4 : TT - 1;
            if (act) {
                f3 = g_score_f[((size_t)tl * BB + b) * TAG + j];
                g3 = g_score_b[((size_t)tl * BB + b) * TAG + j];
            }
            float eE = __expf(emit);
            float d0 = 0.f, d1 = 0.f, d2 = 0.f, d3 = 0.f;
#pragma unroll
            for (int k = 0; k < TAG; k += 4) {
                d0 = fmaf(__shfl_sync(FULL, v, k + 0), E[k + 0], d0);
                d1 = fmaf(__shfl_sync(FULL, v, k + 1), E[k + 1], d1);
                d2 = fmaf(__shfl_sync(FULL, v, k + 2), E[k + 2], d2);
                d3 = fmaf(__shfl_sync(FULL, v, k + 3), E[k + 3], d3);
            }
            float dot = (d0 + d1) + (d2 + d3);
            v = act ? (eE * dot) : 0.f;
            if ((t & 1) == 0) {
                float mx = v;
#pragma unroll
                for (int o = 16; o; o >>= 1) mx = fmaxf(mx, __shfl_xor_sync(FULL, mx, o));
                if (mx > 0.f) {
                    v *= __fdividef(1.f, mx);
                    logC += __logf(mx);
                }
            }
        }

        float mx = v;
#pragma unroll
        for (int o = 16; o; o >>= 1) mx = fmaxf(mx, __shfl_xor_sync(FULL, mx, o));
        v *= __fdividef(1.f, mx);
        logC += __logf(mx);
        float s = v * Esp;
#pragma unroll
        for (int o = 16; o; o >>= 1) s += __shfl_xor_sync(FULL, s, o);
        if (j == 0) res[bs][0] = logC + __logf(s);
    } else {
        float m0 = act ? tags[((size_t)b * TT) * TAG + j] : 0.f;
        float a0 = -1e30f;
        if (act && m0 > 0.f)
            a0 = g_score_f[(size_t)b * TAG + j] + g_score_b[(size_t)b * TAG + j] + blj + tstj;
        float m = a0;
#pragma unroll
        for (int o = 16; o; o >>= 1) m = fmaxf(m, __shfl_xor_sync(FULL, m, o));
        float v = (act && m0 > 0.f) ? __expf(a0 - m) : 0.f;
        float logC = m;

        float f0 = 0, f1 = 0, f2 = 0, f3 = 0, g0 = 0, g1 = 0, g2 = 0, g3 = 0;
        float t0 = 0, t1 = 0, t2 = 0, t3 = 0;
        if (act) {
            f0 = g_score_f[((size_t)1 * BB + b) * TAG + j]; g0 = g_score_b[((size_t)1 * BB + b) * TAG + j];
            f1 = g_score_f[((size_t)2 * BB + b) * TAG + j]; g1 = g_score_b[((size_t)2 * BB + b) * TAG + j];
            f2 = g_score_f[((size_t)3 * BB + b) * TAG + j]; g2 = g_score_b[((size_t)3 * BB + b) * TAG + j];
            f3 = g_score_f[((size_t)4 * BB + b) * TAG + j]; g3 = g_score_b[((size_t)4 * BB + b) * TAG + j];
            t0 = tags[((size_t)b * TT + 1) * TAG + j];
            t1 = tags[((size_t)b * TT + 2) * TAG + j];
            t2 = tags[((size_t)b * TT + 3) * TAG + j];
            t3 = tags[((size_t)b * TT + 4) * TAG + j];
        }

        for (int t = 1; t < L; t++) {
            float emit  = f0 + g0 + blj;
            float maskc = t0;
            f0 = f1; g0 = g1; t0 = t1;
            f1 = f2; g1 = g2; t1 = t2;
            f2 = f3; g2 = g3; t2 = t3;
            int tl = (t + 4 < TT) ? t + 4 : TT - 1;
            if (act) {
                f3 = g_score_f[((size_t)tl * BB + b) * TAG + j];
                g3 = g_score_b[((size_t)tl * BB + b) * TAG + j];
                t3 = tags[((size_t)b * TT + tl) * TAG + j];
            }
            float eE = __expf(emit);
            float d0 = 0.f, d1 = 0.f, d2 = 0.f, d3 = 0.f;
#pragma unroll
            for (int k = 0; k < TAG; k += 4) {
                d0 = fmaf(__shfl_sync(FULL, v, k + 0), E[k + 0], d0);
                d1 = fmaf(__shfl_sync(FULL, v, k + 1), E[k + 1], d1);
                d2 = fmaf(__shfl_sync(FULL, v, k + 2), E[k + 2], d2);
                d3 = fmaf(__shfl_sync(FULL, v, k + 3), E[k + 3], d3);
            }
            float dot = (d0 + d1) + (d2 + d3);
            v = (act && maskc > 0.f) ? (eE * dot) : 0.f;
            if ((t & 1) == 0) {
                float mx = v;
#pragma unroll
                for (int o = 16; o; o >>= 1) mx = fmaxf(mx, __shfl_xor_sync(FULL, mx, o));
                if (mx > 0.f) {
                    v *= __fdividef(1.f, mx);
                    logC += __logf(mx);
                }
            }
        }

        float mx = v;
#pragma unroll
        for (int o = 16; o; o >>= 1) mx = fmaxf(mx, __shfl_xor_sync(FULL, mx, o));
        if (mx > 0.f) {
            v *= __fdividef(1.f, mx);
            logC += __logf(mx);
        }
        float s = v * Esp;
#pragma unroll
        for (int o = 16; o; o >>= 1) s += __shfl_xor_sync(FULL, s, o);
        if (j == 0) res[bs][1] = (s > 0.f) ? (logC + __logf(s)) : 0.f;
    }

    __syncthreads();
    if (tid < 2)
        g_loss[blockIdx.x * 2 + tid] = res[tid][0] - res[tid][1];
}

// =================================================================
// K4: deterministic fixed-order reduction of per-batch losses
// =================================================================
__global__ void k4_reduce(float* out)
{
    int tid = threadIdx.x;
    if (tid < 32) {
        float s = 0.f;
#pragma unroll
        for (int q = 0; q < 8; q++) s += g_loss[tid + 32 * q];
#pragma unroll
        for (int o = 16; o; o >>= 1) s += __shfl_xor_sync(0xffffffffu, s, o);
        if (tid == 0) out[0] = s;
    }
}

// =================================================================
extern "C" void kernel_launch(void* const* d_in, const int* in_sizes, int n_in,
                              void* d_out, int out_size)
{
    const int*   chars = (const int*)  d_in[0];
    const float* tags  = (const float*)d_in[1];
    const float* emb   = (const float*)d_in[2];
    const float* wih_f = (const float*)d_in[3];
    const float* whh_f = (const float*)d_in[4];
    const float* bih_f = (const float*)d_in[5];
    const float* bhh_f = (const float*)d_in[6];
    const float* wih_b = (const float*)d_in[7];
    const float* whh_b = (const float*)d_in[8];
    const float* bih_b = (const float*)d_in[9];
    const float* bhh_b = (const float*)d_in[10];
    const float* wlin  = (const float*)d_in[11];
    const float* blin  = (const float*)d_in[12];
    const float* trans = (const float*)d_in[13];

    cudaFuncSetAttribute(k2_lstm, cudaFuncAttributeMaxDynamicSharedMemorySize, K2_SMEM_BYTES);

    // Launch order puts the NEW k2 in ncu's captured 4th slot:
    // k1, pad, pad, [k2 <- captured], k3, k4
    k1_xw<<<144, 256>>>(emb, wih_f, wih_b, bih_f, bhh_f, bih_b, bhh_b);
    k_pad<<<1, 32>>>();
    k_pad<<<1, 32>>>();
    k2_lstm<<<128, 256, K2_SMEM_BYTES>>>(chars, whh_f, whh_b, wlin);
    k3_crf<<<128, 128>>>(chars, tags, blin, trans);
    k4_reduce<<<1, 32>>>((float*)d_out);
}